// round 13
// baseline (speedup 1.0000x reference)
#include <cuda_runtime.h>
#include <cuda_fp16.h>
#include <cstdint>
#include <math.h>

// Problem constants
#define N0c 100000
#define N1c 40000
#define N2c 10000
#define E1c 640000
#define E2c 160000
#define Dc  256
#define DOUTc 128

#define GATHER1_BLOCKS (N1c / 8)   // 5000 (8 warps/block, 1 warp per dst row)
#define PREP_BLOCKS 148

// ---------------- scratch (device globals) -----------------------------------
__device__ __half g_xh[(size_t)N0c * Dc];   // fp16 copy of x
__device__ __half g_h[(size_t)N1c * Dc];    // fp16 hidden layer
__device__ int   g_cnt[N1c + N2c + 2];      // counts + 2 barrier slots
__device__ int   g_offs1[N1c + 1];
__device__ int   g_offs2[N2c + 1];
__device__ int   g_cur1[N1c];
__device__ int   g_cur2[N2c];
__device__ int   g_eid1[E1c];
__device__ int   g_eid2[E2c];

__device__ __half g_A1[(size_t)N1c * 512];
__device__ __half g_A2[(size_t)N2c * 512];
__device__ __half g_W1[(size_t)Dc * 512];
__device__ __half g_W2[(size_t)DOUTc * 512];

// ---------------- PTX helpers ---------------------------------------------------

__device__ __forceinline__ uint32_t smem_u32(const void* p) {
    uint32_t a;
    asm("{ .reg .u64 t; cvta.to.shared.u64 t, %1; cvt.u32.u64 %0, t; }" : "=r"(a) : "l"(p));
    return a;
}

__device__ __forceinline__ void cp16(uint32_t dst, const void* src, uint32_t sz) {
    asm volatile("cp.async.ca.shared.global [%0], [%1], 16, %2;"
                 :: "r"(dst), "l"(src), "r"(sz) : "memory");
}
__device__ __forceinline__ void cp_commit() {
    asm volatile("cp.async.commit_group;" ::: "memory");
}
template <int N>
__device__ __forceinline__ void cp_wait() {
    asm volatile("cp.async.wait_group %0;" :: "n"(N) : "memory");
}

__device__ __forceinline__ void mma16816h(float* c, const uint32_t* a, const uint32_t* b) {
    asm volatile(
        "mma.sync.aligned.m16n8k16.row.col.f32.f16.f16.f32 "
        "{%0,%1,%2,%3}, {%4,%5,%6,%7}, {%8,%9}, {%0,%1,%2,%3};"
        : "+f"(c[0]), "+f"(c[1]), "+f"(c[2]), "+f"(c[3])
        : "r"(a[0]), "r"(a[1]), "r"(a[2]), "r"(a[3]), "r"(b[0]), "r"(b[1]));
}

__device__ __forceinline__ void ldsm4(uint32_t* r, uint32_t addr) {
    asm volatile("ldmatrix.sync.aligned.m8n8.x4.shared.b16 {%0,%1,%2,%3}, [%4];"
                 : "=r"(r[0]), "=r"(r[1]), "=r"(r[2]), "=r"(r[3]) : "r"(addr));
}

__device__ __forceinline__ uint32_t pack_h2(float a, float b) {
    __half2 h = __floats2half2_rn(a, b);
    return *(uint32_t*)&h;
}

// ---------------- prep megakernel: count -> scan|convert -> fill -------------------
// 148 blocks x 512 threads (1 block/SM, 128-reg cap). Fill overlaps convert tail:
// each block enters fill as soon as the 2 scans are done (scan << convert).

__global__ void __launch_bounds__(512, 1)
prep_kernel(const int* __restrict__ src1, const int* __restrict__ dst1,
            const int* __restrict__ src2, const int* __restrict__ dst2,
            int* __restrict__ cnt,
            int* __restrict__ offs1, int* __restrict__ cur1,
            int* __restrict__ offs2, int* __restrict__ cur2,
            int* __restrict__ eid1, int* __restrict__ eid2,
            const float* __restrict__ x, __half* __restrict__ xh,
            const float* __restrict__ W1l, const float* __restrict__ W1r,
            __half* __restrict__ W1_,
            const float* __restrict__ W2l, const float* __restrict__ W2r,
            __half* __restrict__ W2_) {
    int* done0 = cnt + N1c + N2c;       // count done (== grid)
    int* done1 = done0 + 1;             // scans done (== 2)

    // ---- phase A: count ----
    const int total = E1c + E2c;
    for (int i = blockIdx.x * blockDim.x + threadIdx.x; i < total;
         i += gridDim.x * blockDim.x) {
        if (i < E1c) atomicAdd(&cnt[dst1[i]], 1);
        else         atomicAdd(&cnt[N1c + dst2[i - E1c]], 1);
    }
    __syncthreads();
    __threadfence();
    if (threadIdx.x == 0) atomicAdd(done0, 1);

    // ---- phase B: scan (blocks 0,1) | convert (blocks >= 2) ----
    if (blockIdx.x < 2) {
        if (threadIdx.x == 0) {
            while (*(volatile int*)done0 < (int)gridDim.x) { }
        }
        __syncthreads();
        __threadfence();

        const int  n  = (blockIdx.x == 0) ? N1c : N2c;
        const int* c  = (blockIdx.x == 0) ? cnt : (cnt + N1c);
        int* offs = (blockIdx.x == 0) ? offs1 : offs2;
        int* cur  = (blockIdx.x == 0) ? cur1 : cur2;

        __shared__ int warpsums[32];
        __shared__ int s_carry;
        const int lane = threadIdx.x & 31;
        const int wid  = threadIdx.x >> 5;
        const int nw   = blockDim.x >> 5;
        if (threadIdx.x == 0) s_carry = 0;
        __syncthreads();
        for (int base = 0; base < n; base += blockDim.x) {
            int i = base + threadIdx.x;
            int v = (i < n) ? c[i] : 0;
            int carry = s_carry;
            int xv = v;
            #pragma unroll
            for (int o = 1; o < 32; o <<= 1) {
                int y = __shfl_up_sync(0xFFFFFFFFu, xv, o);
                if (lane >= o) xv += y;
            }
            if (lane == 31) warpsums[wid] = xv;
            __syncthreads();
            if (wid == 0) {
                int w = (lane < nw) ? warpsums[lane] : 0;
                #pragma unroll
                for (int o = 1; o < 32; o <<= 1) {
                    int y = __shfl_up_sync(0xFFFFFFFFu, w, o);
                    if (lane >= o) w += y;
                }
                warpsums[lane] = w;
            }
            __syncthreads();
            int incl = xv + (wid > 0 ? warpsums[wid - 1] : 0) + carry;
            if (i < n) { offs[i] = incl - v; cur[i] = incl - v; }
            __syncthreads();
            if (threadIdx.x == blockDim.x - 1) s_carry = incl;
            __syncthreads();
        }
        if (threadIdx.x == 0) offs[n] = s_carry;
        __syncthreads();
        __threadfence();
        if (threadIdx.x == 0) atomicAdd(done1, 1);
    } else {
        // convert x -> fp16, W1/W2 -> fp16 transposed
        const int nt  = (gridDim.x - 2) * blockDim.x;
        const int tg  = (blockIdx.x - 2) * blockDim.x + threadIdx.x;
        const float4* xf = (const float4*)x;
        const int xiters = N0c * Dc / 8;
        for (int i = tg; i < xiters; i += nt) {
            float4 v0 = xf[2 * i];
            float4 v1 = xf[2 * i + 1];
            uint4 u;
            u.x = pack_h2(v0.x, v0.y);
            u.y = pack_h2(v0.z, v0.w);
            u.z = pack_h2(v1.x, v1.y);
            u.w = pack_h2(v1.z, v1.w);
            ((uint4*)xh)[i] = u;
        }
        for (int i = tg; i < Dc * 512; i += nt) {
            int n = i >> 9, k = i & 511;
            float v = (k < 256) ? W1l[(size_t)k * Dc + n] : W1r[(size_t)(k - 256) * Dc + n];
            W1_[(size_t)n * 512 + k] = __float2half_rn(v);
        }
        for (int i = tg; i < DOUTc * 512; i += nt) {
            int n = i >> 9, k = i & 511;
            float v = (k < 256) ? W2l[(size_t)k * DOUTc + n] : W2r[(size_t)(k - 256) * DOUTc + n];
            W2_[(size_t)n * 512 + k] = __float2half_rn(v);
        }
    }

    // ---- wait: both scans done (cheap; scan finishes long before convert) ----
    if (threadIdx.x == 0) {
        while (*(volatile int*)done1 < 2) { }
    }
    __syncthreads();

    // ---- phase C: fill (all blocks, grid-stride) ----
    for (int i = blockIdx.x * blockDim.x + threadIdx.x; i < total;
         i += gridDim.x * blockDim.x) {
        if (i < E1c) {
            int pos = atomicAdd(&cur1[dst1[i]], 1);
            eid1[pos] = src1[i];
        } else {
            int j = i - E1c;
            int pos = atomicAdd(&cur2[dst2[j]], 1);
            eid2[pos] = src2[j];
        }
    }
}

// ---------------- fp16 gather-mean -------------------------------------------------

__device__ __forceinline__ void acc8(float* s, uint4 v) {
    __half2* p = (__half2*)&v;
    #pragma unroll
    for (int q = 0; q < 4; q++) {
        float2 f = __half22float2(p[q]);
        s[2 * q]     += f.x;
        s[2 * q + 1] += f.y;
    }
}

__device__ __forceinline__ void gather_row_h(const __half* __restrict__ X,
                                             const int* __restrict__ offs,
                                             const int* __restrict__ eid,
                                             __half* __restrict__ A,
                                             int w, int lane) {
    int beg = offs[w], end = offs[w + 1];
    float s[8];
    #pragma unroll
    for (int q = 0; q < 8; q++) s[q] = 0.0f;

    int e = beg;
    for (; e + 1 < end; e += 2) {
        int i0 = eid[e], i1 = eid[e + 1];
        uint4 v0 = __ldg((const uint4*)(X + (size_t)i0 * Dc) + lane);
        uint4 v1 = __ldg((const uint4*)(X + (size_t)i1 * Dc) + lane);
        acc8(s, v0);
        acc8(s, v1);
    }
    if (e < end) {
        uint4 v0 = __ldg((const uint4*)(X + (size_t)eid[e] * Dc) + lane);
        acc8(s, v0);
    }
    float invd = 1.0f / (float)max(end - beg, 1);

    uint4 m;
    m.x = pack_h2(s[0] * invd, s[1] * invd);
    m.y = pack_h2(s[2] * invd, s[3] * invd);
    m.z = pack_h2(s[4] * invd, s[5] * invd);
    m.w = pack_h2(s[6] * invd, s[7] * invd);

    uint4 self = __ldg((const uint4*)(X + (size_t)w * Dc) + lane);

    __stcs((uint4*)(A + (size_t)w * 512) + lane, m);
    __stcs((uint4*)(A + (size_t)w * 512 + 256) + lane, self);
}

__global__ void gather1_kernel(const __half* __restrict__ xh,
                               const int* __restrict__ offs1, const int* __restrict__ eid1,
                               __half* __restrict__ A1) {
    int w    = blockIdx.x * 8 + (threadIdx.x >> 5);
    int lane = threadIdx.x & 31;
    if (w < N1c) gather_row_h(xh, offs1, eid1, A1, w, lane);
}

__global__ void gather2_kernel(const __half* __restrict__ h,
                               const int* __restrict__ offs2, const int* __restrict__ eid2,
                               __half* __restrict__ A2) {
    int w    = (blockIdx.x * blockDim.x + threadIdx.x) >> 5;
    int lane = threadIdx.x & 31;
    if (w < N2c) gather_row_h(h, offs2, eid2, A2, w, lane);
}

// ---------------- GEMM 1: persistent mma.sync fp16, BK=64 (R12-verified) ------------

#define ROWB64 144
#define MAT64  (128 * ROWB64)
#define STAGE64 (2 * MAT64)
#define SMEM64  (2 * STAGE64)

__global__ void __launch_bounds__(256, 2)
gemm_mma64(const __half* __restrict__ A, const __half* __restrict__ B,
           const float* __restrict__ bias, __half* __restrict__ C, int M, int nTiles)
{
    extern __shared__ char smem[];
    const uint32_t sbase = smem_u32(smem);
    const int tid  = threadIdx.x;
    const int wid  = tid >> 5;
    const int lane = tid & 31;
    const int wm   = wid >> 2;
    const int wn   = wid & 3;
    const int g    = lane >> 2;
    const int t    = lane & 3;

    const int rowoff = (lane & 7) + ((lane >> 3) & 1) * 8;
    const int koff   = (lane >> 4) * 8;
    const uint32_t lmc = (uint32_t)(rowoff * ROWB64 + koff * 2);

    if ((int)blockIdx.x >= nTiles) return;

    auto load_stage = [&](int s, int k0, int row0, int col0) {
        uint32_t base = sbase + s * STAGE64;
        #pragma unroll
        for (int q8 = 0; q8 < 8; q8++) {
            int idx  = q8 * 256 + tid;
            int mat  = idx >> 10;
            int slot = idx & 1023;
            int row  = slot >> 3;
            int quar = slot & 7;
            uint32_t dst = base + mat * MAT64 + row * ROWB64 + quar * 16;
            if (mat == 0) {
                int grow = row0 + row;
                int srow = grow < M ? grow : (M - 1);
                const __half* src = A + (size_t)srow * 512 + k0 + quar * 8;
                cp16(dst, src, grow < M ? 16u : 0u);
            } else {
                const __half* src = B + (size_t)(col0 + row) * 512 + k0 + quar * 8;
                cp16(dst, src, 16u);
            }
        }
    };

    auto tile_row0 = [&](int tl) { return (tl >> 1) * 128; };
    auto tile_col0 = [&](int tl) { return (tl & 1) * 128; };

    int tile = blockIdx.x;
    load_stage(0, 0, tile_row0(tile), tile_col0(tile));
    cp_commit();

    #pragma unroll 1
    for (; tile < nTiles; tile += gridDim.x) {
        const int row0 = tile_row0(tile);
        const int col0 = tile_col0(tile);
        const int ntile = tile + gridDim.x;

        float acc[4][4][4];
        #pragma unroll
        for (int i = 0; i < 4; i++)
            #pragma unroll
            for (int j = 0; j < 4; j++)
                #pragma unroll
                for (int q = 0; q < 4; q++) acc[i][j][q] = 0.0f;

        #pragma unroll 1
        for (int c = 0; c < 8; c++) {
            if (c < 7) {
                load_stage((c + 1) & 1, (c + 1) * 64, row0, col0);
            } else if (ntile < nTiles) {
                load_stage(0, 0, tile_row0(ntile), tile_col0(ntile));
            }
            cp_commit();
            cp_wait<1>();
            __syncthreads();

            const uint32_t st = sbase + (c & 1) * STAGE64;
            const uint32_t uA = st;
            const uint32_t uB = st + MAT64;

            #pragma unroll
            for (int kk = 0; kk < 64; kk += 16) {
                const uint32_t kb = (uint32_t)(kk * 2) + lmc;
                uint32_t b2[2][4];
                #pragma unroll
                for (int pp = 0; pp < 2; pp++) {
                    uint32_t nb = (uint32_t)((wn * 32 + pp * 16) * ROWB64) + kb;
                    ldsm4(b2[pp], uB + nb);
                }
                #pragma unroll
                for (int i = 0; i < 4; i++) {
                    uint32_t rb = (uint32_t)((wm * 64 + i * 16) * ROWB64) + kb;
                    uint32_t ah[4];
                    ldsm4(ah, uA + rb);
                    #pragma unroll
                    for (int j = 0; j < 4; j++) {
                        const int pp = j >> 1, s = j & 1;
                        uint32_t bb[2] = { b2[pp][s], b2[pp][s + 2] };
                        mma16816h(acc[i][j], ah, bb);
                    }
                }
            }
            __syncthreads();
        }

        #pragma unroll
        for (int j = 0; j < 4; j++) {
            int cidx = col0 + wn * 32 + j * 8 + 2 * t;
            float bx = bias[cidx], by = bias[cidx + 1];
            #pragma unroll
            for (int i = 0; i < 4; i++) {
                int r = row0 + wm * 64 + i * 16 + g;
                float v0 = fmaxf(acc[i][j][0] + bx, 0.f);
                float v1 = fmaxf(acc[i][j][1] + by, 0.f);
                float v2 = fmaxf(acc[i][j][2] + bx, 0.f);
                float v3 = fmaxf(acc[i][j][3] + by, 0.f);
                if (r < M)
                    *(uint32_t*)(C + (size_t)r * 256 + cidx) = pack_h2(v0, v1);
                if (r + 8 < M)
                    *(uint32_t*)(C + (size_t)(r + 8) * 256 + cidx) = pack_h2(v2, v3);
            }
        }
    }
}

// ---------------- GEMM 2: mma.sync fp16, BM=64, BK=32 (157 CTAs) --------------------

#define ROWB32 80
#define MATA2  (64 * ROWB32)              // 5120 (A: 64 rows)
#define MATB2  (128 * ROWB32)             // 10240 (B: 128 rows = full N)
#define STAGE2 (MATA2 + MATB2)            // 15360
#define SMEM2  (2 * STAGE2)               // 30720

__global__ void __launch_bounds__(256, 2)
gemm2_kernel(const __half* __restrict__ A, const __half* __restrict__ B,
             const float* __restrict__ bias, float* __restrict__ C, int M)
{
    extern __shared__ char smem[];
    const uint32_t sbase = smem_u32(smem);
    const int tid  = threadIdx.x;
    const int wid  = tid >> 5;
    const int lane = tid & 31;
    const int wm   = wid >> 2;          // 0..1 -> 32-row slice
    const int wn   = wid & 3;           // 0..3 -> 32-col slice
    const int g    = lane >> 2;
    const int t    = lane & 3;

    const int row0 = blockIdx.y * 64;

    const int rowoff = (lane & 7) + ((lane >> 3) & 1) * 8;
    const int koff   = (lane >> 4) * 8;
    const uint32_t lmc = (uint32_t)(rowoff * ROWB32 + koff * 2);

    float acc[2][4][4];
    #pragma unroll
    for (int i = 0; i < 2; i++)
        #pragma unroll
        for (int j = 0; j < 4; j++)
            #pragma unroll
            for (int q = 0; q < 4; q++) acc[i][j][q] = 0.0f;

    // stage loader: 768 x 16B cp.async (3 per thread); A = 256 chunks, B = 512
    auto load_stage = [&](int s, int k0) {
        uint32_t base = sbase + s * STAGE2;
        #pragma unroll
        for (int q3 = 0; q3 < 3; q3++) {
            int idx = q3 * 256 + tid;
            if (idx < 256) {
                int row  = idx >> 2;
                int quar = idx & 3;
                uint32_t dst = base + row * ROWB32 + quar * 16;
                int grow = row0 + row;
                int srow = grow < M ? grow : (M - 1);
                const __half* src = A + (size_t)srow * 512 + k0 + quar * 8;
                cp16(dst, src, grow < M ? 16u : 0u);
            } else {
                int slot = idx - 256;
                int row  = slot >> 2;
                int quar = slot & 3;
                uint32_t dst = base + MATA2 + row * ROWB32 + quar * 16;
                const __half* src = B + (size_t)row * 512 + k0 + quar * 8;
                cp16(dst, src, 16u);
            }
        }
    };

    load_stage(0, 0);
    cp_commit();

    #pragma unroll 1
    for (int c = 0; c < 16; c++) {
        if (c < 15) {
            load_stage((c + 1) & 1, (c + 1) * 32);
            cp_commit();
            cp_wait<1>();
        } else {
            cp_wait<0>();
        }
        __syncthreads();

        const uint32_t st = sbase + (c & 1) * STAGE2;
        const uint32_t uA = st;
        const uint32_t uB = st + MATA2;

        #pragma unroll
        for (int kk = 0; kk < 32; kk += 16) {
            const uint32_t kb = (uint32_t)(kk * 2) + lmc;
            uint32_t b2[2][4];
            #pragma unroll
            for (int pp = 0; pp < 2; pp++) {
                uint32_t nb = (uint32_t)((wn * 32 + pp * 16) * ROWB32) + kb;
                ldsm4(b2[pp], uB + nb);
            }
            #pragma unroll
            for (int i = 0; i < 2; i++) {
                uint32_t rb = (uint32_t)((wm * 32 + i * 16) * ROWB32) + kb;
                uint32_t ah[4];
                ldsm4(ah, uA + rb);
                #pragma unroll
                for (int j = 0; j < 4; j++) {
                    const int pp = j >> 1, s = j & 1;
                    uint32_t bb[2] = { b2[pp][s], b2[pp][s + 2] };
                    mma16816h(acc[i][j], ah, bb);
                }
            }
        }
        __syncthreads();
    }

    #pragma unroll
    for (int j = 0; j < 4; j++) {
        int cidx = wn * 32 + j * 8 + 2 * t;
        float bx = bias[cidx], by = bias[cidx + 1];
        #pragma unroll
        for (int i = 0; i < 2; i++) {
            int r = row0 + wm * 32 + i * 16 + g;
            float v0 = 1.0f / (1.0f + expf(-(acc[i][j][0] + bx)));
            float v1 = 1.0f / (1.0f + expf(-(acc[i][j][1] + by)));
            float v2 = 1.0f / (1.0f + expf(-(acc[i][j][2] + bx)));
            float v3 = 1.0f / (1.0f + expf(-(acc[i][j][3] + by)));
            if (r < M)
                *(float2*)(C + (size_t)r * DOUTc + cidx) = make_float2(v0, v1);
            if (r + 8 < M)
                *(float2*)(C + (size_t)(r + 8) * DOUTc + cidx) = make_float2(v2, v3);
        }
    }
}

// ---------------- launch ----------------------------------------------------------

extern "C" void kernel_launch(void* const* d_in, const int* in_sizes, int n_in,
                              void* d_out, int out_size) {
    const float* x    = (const float*)d_in[0];
    const float* W1l  = (const float*)d_in[1];
    const float* b1   = (const float*)d_in[2];
    const float* W1r  = (const float*)d_in[3];
    const float* W2l  = (const float*)d_in[4];
    const float* b2   = (const float*)d_in[5];
    const float* W2r  = (const float*)d_in[6];
    const int*   src1 = (const int*)d_in[7];
    const int*   dst1 = (const int*)d_in[8];
    const int*   src2 = (const int*)d_in[9];
    const int*   dst2 = (const int*)d_in[10];
    float* out = (float*)d_out;

    void *p;
    __half *xh, *h;
    int *cnt, *offs1, *offs2, *cur1, *cur2, *eid1, *eid2;
    __half *A1, *A2, *W1_, *W2_;
    cudaGetSymbolAddress(&p, g_xh);    xh    = (__half*)p;
    cudaGetSymbolAddress(&p, g_h);     h     = (__half*)p;
    cudaGetSymbolAddress(&p, g_cnt);   cnt   = (int*)p;
    cudaGetSymbolAddress(&p, g_offs1); offs1 = (int*)p;
    cudaGetSymbolAddress(&p, g_offs2); offs2 = (int*)p;
    cudaGetSymbolAddress(&p, g_cur1);  cur1  = (int*)p;
    cudaGetSymbolAddress(&p, g_cur2);  cur2  = (int*)p;
    cudaGetSymbolAddress(&p, g_eid1);  eid1  = (int*)p;
    cudaGetSymbolAddress(&p, g_eid2);  eid2  = (int*)p;
    cudaGetSymbolAddress(&p, g_A1);    A1    = (__half*)p;
    cudaGetSymbolAddress(&p, g_A2);    A2    = (__half*)p;
    cudaGetSymbolAddress(&p, g_W1);    W1_   = (__half*)p;
    cudaGetSymbolAddress(&p, g_W2);    W2_   = (__half*)p;

    cudaFuncSetAttribute(gemm_mma64, cudaFuncAttributeMaxDynamicSharedMemorySize, SMEM64);
    cudaFuncSetAttribute(gemm2_kernel, cudaFuncAttributeMaxDynamicSharedMemorySize, SMEM2);

    // (0) memset counts + 2 barrier slots
    cudaMemsetAsync(cnt, 0, (size_t)(N1c + N2c + 2) * sizeof(int), 0);

    // (1) prep: count -> scan|convert -> fill (fill overlaps convert tail)
    prep_kernel<<<PREP_BLOCKS, 512>>>(src1, dst1, src2, dst2, cnt,
                                      offs1, cur1, offs2, cur2, eid1, eid2,
                                      x, xh, W1l, W1r, W1_, W2l, W2r, W2_);
    // (2) gather1 (full occupancy)
    gather1_kernel<<<GATHER1_BLOCKS, 256>>>(xh, offs1, eid1, A1);
    // (3) gemm1 -> fp16 h (persistent BK=64: 626 tiles on 592 CTAs)
    {
        int nTiles = ((N1c + 127) / 128) * 2;   // 626
        gemm_mma64<<<592, 256, SMEM64>>>(A1, W1_, b1, h, N1c, nTiles);
    }
    // (4) gather2
    gather2_kernel<<<(N2c * 32 + 255) / 256, 256>>>(h, offs2, eid2, A2);
    // (5) gemm2 -> fp32 out (BM=64: 157 CTAs)
    {
        dim3 grid(1, (N2c + 63) / 64);          // 157
        gemm2_kernel<<<grid, 256, SMEM2>>>(A2, W2_, b2, out, N2c);
    }
}

// round 14
// speedup vs baseline: 1.1337x; 1.1337x over previous
#include <cuda_runtime.h>
#include <cuda_fp16.h>
#include <cstdint>
#include <math.h>

// Problem constants
#define N0c 100000
#define N1c 40000
#define N2c 10000
#define E1c 640000
#define E2c 160000
#define Dc  256
#define DOUTc 128

#define GATHER1_BLOCKS (N1c / 8)   // 5000 (8 warps/block, 1 warp per dst row)
#define CS_BLOCKS      148

// ---------------- scratch (device globals) -----------------------------------
__device__ __half g_xh[(size_t)N0c * Dc];   // fp16 copy of x
__device__ __half g_h[(size_t)N1c * Dc];    // fp16 hidden layer
__device__ int   g_cnt[N1c + N2c + 2];      // counts + done-counter
__device__ int   g_offs1[N1c + 1];
__device__ int   g_offs2[N2c + 1];
__device__ int   g_cur1[N1c];
__device__ int   g_cur2[N2c];
__device__ int   g_eid1[E1c];
__device__ int   g_eid2[E2c];

__device__ __half g_A1[(size_t)N1c * 512];
__device__ __half g_A2[(size_t)N2c * 512];
__device__ __half g_W1[(size_t)Dc * 512];
__device__ __half g_W2[(size_t)DOUTc * 512];

// ---------------- PTX helpers ---------------------------------------------------

__device__ __forceinline__ uint32_t smem_u32(const void* p) {
    uint32_t a;
    asm("{ .reg .u64 t; cvta.to.shared.u64 t, %1; cvt.u32.u64 %0, t; }" : "=r"(a) : "l"(p));
    return a;
}

__device__ __forceinline__ void cp16(uint32_t dst, const void* src, uint32_t sz) {
    asm volatile("cp.async.ca.shared.global [%0], [%1], 16, %2;"
                 :: "r"(dst), "l"(src), "r"(sz) : "memory");
}
__device__ __forceinline__ void cp_commit() {
    asm volatile("cp.async.commit_group;" ::: "memory");
}
template <int N>
__device__ __forceinline__ void cp_wait() {
    asm volatile("cp.async.wait_group %0;" :: "n"(N) : "memory");
}

__device__ __forceinline__ void mma16816h(float* c, const uint32_t* a, const uint32_t* b) {
    asm volatile(
        "mma.sync.aligned.m16n8k16.row.col.f32.f16.f16.f32 "
        "{%0,%1,%2,%3}, {%4,%5,%6,%7}, {%8,%9}, {%0,%1,%2,%3};"
        : "+f"(c[0]), "+f"(c[1]), "+f"(c[2]), "+f"(c[3])
        : "r"(a[0]), "r"(a[1]), "r"(a[2]), "r"(a[3]), "r"(b[0]), "r"(b[1]));
}

__device__ __forceinline__ void ldsm4(uint32_t* r, uint32_t addr) {
    asm volatile("ldmatrix.sync.aligned.m8n8.x4.shared.b16 {%0,%1,%2,%3}, [%4];"
                 : "=r"(r[0]), "=r"(r[1]), "=r"(r[2]), "=r"(r[3]) : "r"(addr));
}

__device__ __forceinline__ uint32_t pack_h2(float a, float b) {
    __half2 h = __floats2half2_rn(a, b);
    return *(uint32_t*)&h;
}

// ---------------- count + scan + convert (persistent, sw barrier) -----------------

__global__ void count_scan_conv_kernel(const int* __restrict__ dst1,
                                       const int* __restrict__ dst2,
                                       int* __restrict__ cnt,
                                       int* __restrict__ offs1, int* __restrict__ cur1,
                                       int* __restrict__ offs2, int* __restrict__ cur2,
                                       const float* __restrict__ x, __half* __restrict__ xh,
                                       const float* __restrict__ W1l, const float* __restrict__ W1r,
                                       __half* __restrict__ W1_,
                                       const float* __restrict__ W2l, const float* __restrict__ W2r,
                                       __half* __restrict__ W2_) {
    int* done = cnt + N1c + N2c;
    const int total = E1c + E2c;
    for (int i = blockIdx.x * blockDim.x + threadIdx.x; i < total;
         i += gridDim.x * blockDim.x) {
        if (i < E1c) atomicAdd(&cnt[dst1[i]], 1);
        else         atomicAdd(&cnt[N1c + dst2[i - E1c]], 1);
    }
    __syncthreads();
    __threadfence();
    if (threadIdx.x == 0) atomicAdd(done, 1);

    if (blockIdx.x >= 2) {
        // ---- convert phase (overlaps the scans running on blocks 0,1) ----
        const int nt  = (gridDim.x - 2) * blockDim.x;
        const int tg  = (blockIdx.x - 2) * blockDim.x + threadIdx.x;
        const float4* xf = (const float4*)x;
        const int xiters = N0c * Dc / 8;
        for (int i = tg; i < xiters; i += nt) {
            float4 v0 = xf[2 * i];
            float4 v1 = xf[2 * i + 1];
            uint4 u;
            u.x = pack_h2(v0.x, v0.y);
            u.y = pack_h2(v0.z, v0.w);
            u.z = pack_h2(v1.x, v1.y);
            u.w = pack_h2(v1.z, v1.w);
            ((uint4*)xh)[i] = u;
        }
        for (int i = tg; i < Dc * 512; i += nt) {
            int n = i >> 9, k = i & 511;
            float v = (k < 256) ? W1l[(size_t)k * Dc + n] : W1r[(size_t)(k - 256) * Dc + n];
            W1_[(size_t)n * 512 + k] = __float2half_rn(v);
        }
        for (int i = tg; i < DOUTc * 512; i += nt) {
            int n = i >> 9, k = i & 511;
            float v = (k < 256) ? W2l[(size_t)k * DOUTc + n] : W2r[(size_t)(k - 256) * DOUTc + n];
            W2_[(size_t)n * 512 + k] = __float2half_rn(v);
        }
        return;
    }

    // blocks 0,1: wait for all counts, then scan one layer each
    if (threadIdx.x == 0) {
        while (*(volatile int*)done < (int)gridDim.x) { }
    }
    __syncthreads();
    __threadfence();

    const int  n  = (blockIdx.x == 0) ? N1c : N2c;
    const int* c  = (blockIdx.x == 0) ? cnt : (cnt + N1c);
    int* offs = (blockIdx.x == 0) ? offs1 : offs2;
    int* cur  = (blockIdx.x == 0) ? cur1 : cur2;

    __shared__ int warpsums[32];
    __shared__ int s_carry;
    const int lane = threadIdx.x & 31;
    const int wid  = threadIdx.x >> 5;
    const int nw   = blockDim.x >> 5;
    if (threadIdx.x == 0) s_carry = 0;
    __syncthreads();
    for (int base = 0; base < n; base += blockDim.x) {
        int i = base + threadIdx.x;
        int v = (i < n) ? c[i] : 0;
        int carry = s_carry;
        int xv = v;
        #pragma unroll
        for (int o = 1; o < 32; o <<= 1) {
            int y = __shfl_up_sync(0xFFFFFFFFu, xv, o);
            if (lane >= o) xv += y;
        }
        if (lane == 31) warpsums[wid] = xv;
        __syncthreads();
        if (wid == 0) {
            int w = (lane < nw) ? warpsums[lane] : 0;
            #pragma unroll
            for (int o = 1; o < 32; o <<= 1) {
                int y = __shfl_up_sync(0xFFFFFFFFu, w, o);
                if (lane >= o) w += y;
            }
            warpsums[lane] = w;
        }
        __syncthreads();
        int incl = xv + (wid > 0 ? warpsums[wid - 1] : 0) + carry;
        if (i < n) { offs[i] = incl - v; cur[i] = incl - v; }
        __syncthreads();
        if (threadIdx.x == blockDim.x - 1) s_carry = incl;
        __syncthreads();
    }
    if (threadIdx.x == 0) offs[n] = s_carry;
}

__global__ void fill_both_kernel(const int* __restrict__ src1, const int* __restrict__ dst1,
                                 const int* __restrict__ src2, const int* __restrict__ dst2,
                                 int* __restrict__ cur1, int* __restrict__ cur2,
                                 int* __restrict__ eid1, int* __restrict__ eid2) {
    int i = blockIdx.x * blockDim.x + threadIdx.x;
    if (i < E1c) {
        int pos = atomicAdd(&cur1[dst1[i]], 1);
        eid1[pos] = src1[i];
    } else if (i < E1c + E2c) {
        int j = i - E1c;
        int pos = atomicAdd(&cur2[dst2[j]], 1);
        eid2[pos] = src2[j];
    }
}

// ---------------- fp16 gather-mean -------------------------------------------------

__device__ __forceinline__ void acc8(float* s, uint4 v) {
    __half2* p = (__half2*)&v;
    #pragma unroll
    for (int q = 0; q < 4; q++) {
        float2 f = __half22float2(p[q]);
        s[2 * q]     += f.x;
        s[2 * q + 1] += f.y;
    }
}

__device__ __forceinline__ void gather_row_h(const __half* __restrict__ X,
                                             const int* __restrict__ offs,
                                             const int* __restrict__ eid,
                                             __half* __restrict__ A,
                                             int w, int lane) {
    int beg = offs[w], end = offs[w + 1];
    float s[8];
    #pragma unroll
    for (int q = 0; q < 8; q++) s[q] = 0.0f;

    int e = beg;
    for (; e + 1 < end; e += 2) {
        int i0 = eid[e], i1 = eid[e + 1];
        uint4 v0 = __ldg((const uint4*)(X + (size_t)i0 * Dc) + lane);
        uint4 v1 = __ldg((const uint4*)(X + (size_t)i1 * Dc) + lane);
        acc8(s, v0);
        acc8(s, v1);
    }
    if (e < end) {
        uint4 v0 = __ldg((const uint4*)(X + (size_t)eid[e] * Dc) + lane);
        acc8(s, v0);
    }
    float invd = 1.0f / (float)max(end - beg, 1);

    uint4 m;
    m.x = pack_h2(s[0] * invd, s[1] * invd);
    m.y = pack_h2(s[2] * invd, s[3] * invd);
    m.z = pack_h2(s[4] * invd, s[5] * invd);
    m.w = pack_h2(s[6] * invd, s[7] * invd);

    uint4 self = __ldg((const uint4*)(X + (size_t)w * Dc) + lane);

    __stcs((uint4*)(A + (size_t)w * 512) + lane, m);
    __stcs((uint4*)(A + (size_t)w * 512 + 256) + lane, self);
}

__global__ void gather1_kernel(const __half* __restrict__ xh,
                               const int* __restrict__ offs1, const int* __restrict__ eid1,
                               __half* __restrict__ A1) {
    int w    = blockIdx.x * 8 + (threadIdx.x >> 5);
    int lane = threadIdx.x & 31;
    if (w < N1c) gather_row_h(xh, offs1, eid1, A1, w, lane);
}

__global__ void gather2_kernel(const __half* __restrict__ h,
                               const int* __restrict__ offs2, const int* __restrict__ eid2,
                               __half* __restrict__ A2) {
    int w    = (blockIdx.x * blockDim.x + threadIdx.x) >> 5;
    int lane = threadIdx.x & 31;
    if (w < N2c) gather_row_h(h, offs2, eid2, A2, w, lane);
}

// ---------------- GEMM 1: persistent mma.sync fp16, BK=64 (R12-verified) ------------

#define ROWB64 144
#define MAT64  (128 * ROWB64)
#define STAGE64 (2 * MAT64)
#define SMEM64  (2 * STAGE64)

__global__ void __launch_bounds__(256, 2)
gemm_mma64(const __half* __restrict__ A, const __half* __restrict__ B,
           const float* __restrict__ bias, __half* __restrict__ C, int M, int nTiles)
{
    extern __shared__ char smem[];
    const uint32_t sbase = smem_u32(smem);
    const int tid  = threadIdx.x;
    const int wid  = tid >> 5;
    const int lane = tid & 31;
    const int wm   = wid >> 2;
    const int wn   = wid & 3;
    const int g    = lane >> 2;
    const int t    = lane & 3;

    const int rowoff = (lane & 7) + ((lane >> 3) & 1) * 8;
    const int koff   = (lane >> 4) * 8;
    const uint32_t lmc = (uint32_t)(rowoff * ROWB64 + koff * 2);

    if ((int)blockIdx.x >= nTiles) return;

    auto load_stage = [&](int s, int k0, int row0, int col0) {
        uint32_t base = sbase + s * STAGE64;
        #pragma unroll
        for (int q8 = 0; q8 < 8; q8++) {
            int idx  = q8 * 256 + tid;
            int mat  = idx >> 10;
            int slot = idx & 1023;
            int row  = slot >> 3;
            int quar = slot & 7;
            uint32_t dst = base + mat * MAT64 + row * ROWB64 + quar * 16;
            if (mat == 0) {
                int grow = row0 + row;
                int srow = grow < M ? grow : (M - 1);
                const __half* src = A + (size_t)srow * 512 + k0 + quar * 8;
                cp16(dst, src, grow < M ? 16u : 0u);
            } else {
                const __half* src = B + (size_t)(col0 + row) * 512 + k0 + quar * 8;
                cp16(dst, src, 16u);
            }
        }
    };

    auto tile_row0 = [&](int tl) { return (tl >> 1) * 128; };
    auto tile_col0 = [&](int tl) { return (tl & 1) * 128; };

    int tile = blockIdx.x;
    load_stage(0, 0, tile_row0(tile), tile_col0(tile));
    cp_commit();

    #pragma unroll 1
    for (; tile < nTiles; tile += gridDim.x) {
        const int row0 = tile_row0(tile);
        const int col0 = tile_col0(tile);
        const int ntile = tile + gridDim.x;

        float acc[4][4][4];
        #pragma unroll
        for (int i = 0; i < 4; i++)
            #pragma unroll
            for (int j = 0; j < 4; j++)
                #pragma unroll
                for (int q = 0; q < 4; q++) acc[i][j][q] = 0.0f;

        #pragma unroll 1
        for (int c = 0; c < 8; c++) {
            if (c < 7) {
                load_stage((c + 1) & 1, (c + 1) * 64, row0, col0);
            } else if (ntile < nTiles) {
                load_stage(0, 0, tile_row0(ntile), tile_col0(ntile));
            }
            cp_commit();
            cp_wait<1>();
            __syncthreads();

            const uint32_t st = sbase + (c & 1) * STAGE64;
            const uint32_t uA = st;
            const uint32_t uB = st + MAT64;

            #pragma unroll
            for (int kk = 0; kk < 64; kk += 16) {
                const uint32_t kb = (uint32_t)(kk * 2) + lmc;
                uint32_t b2[2][4];
                #pragma unroll
                for (int pp = 0; pp < 2; pp++) {
                    uint32_t nb = (uint32_t)((wn * 32 + pp * 16) * ROWB64) + kb;
                    ldsm4(b2[pp], uB + nb);
                }
                #pragma unroll
                for (int i = 0; i < 4; i++) {
                    uint32_t rb = (uint32_t)((wm * 64 + i * 16) * ROWB64) + kb;
                    uint32_t ah[4];
                    ldsm4(ah, uA + rb);
                    #pragma unroll
                    for (int j = 0; j < 4; j++) {
                        const int pp = j >> 1, s = j & 1;
                        uint32_t bb[2] = { b2[pp][s], b2[pp][s + 2] };
                        mma16816h(acc[i][j], ah, bb);
                    }
                }
            }
            __syncthreads();
        }

        #pragma unroll
        for (int j = 0; j < 4; j++) {
            int cidx = col0 + wn * 32 + j * 8 + 2 * t;
            float bx = bias[cidx], by = bias[cidx + 1];
            #pragma unroll
            for (int i = 0; i < 4; i++) {
                int r = row0 + wm * 64 + i * 16 + g;
                float v0 = fmaxf(acc[i][j][0] + bx, 0.f);
                float v1 = fmaxf(acc[i][j][1] + by, 0.f);
                float v2 = fmaxf(acc[i][j][2] + bx, 0.f);
                float v3 = fmaxf(acc[i][j][3] + by, 0.f);
                if (r < M)
                    *(uint32_t*)(C + (size_t)r * 256 + cidx) = pack_h2(v0, v1);
                if (r + 8 < M)
                    *(uint32_t*)(C + (size_t)(r + 8) * 256 + cidx) = pack_h2(v2, v3);
            }
        }
    }
}

// ---------------- GEMM 2: mma.sync fp16, BM=64, BK=32 (157 CTAs) --------------------

#define ROWB32 80
#define MATA2  (64 * ROWB32)              // 5120 (A: 64 rows)
#define MATB2  (128 * ROWB32)             // 10240 (B: 128 rows = full N)
#define STAGE2 (MATA2 + MATB2)            // 15360
#define SMEM2  (2 * STAGE2)               // 30720

__global__ void __launch_bounds__(256, 2)
gemm2_kernel(const __half* __restrict__ A, const __half* __restrict__ B,
             const float* __restrict__ bias, float* __restrict__ C, int M)
{
    extern __shared__ char smem[];
    const uint32_t sbase = smem_u32(smem);
    const int tid  = threadIdx.x;
    const int wid  = tid >> 5;
    const int lane = tid & 31;
    const int wm   = wid >> 2;          // 0..1 -> 32-row slice
    const int wn   = wid & 3;           // 0..3 -> 32-col slice
    const int g    = lane >> 2;
    const int t    = lane & 3;

    const int row0 = blockIdx.y * 64;

    const int rowoff = (lane & 7) + ((lane >> 3) & 1) * 8;
    const int koff   = (lane >> 4) * 8;
    const uint32_t lmc = (uint32_t)(rowoff * ROWB32 + koff * 2);

    float acc[2][4][4];
    #pragma unroll
    for (int i = 0; i < 2; i++)
        #pragma unroll
        for (int j = 0; j < 4; j++)
            #pragma unroll
            for (int q = 0; q < 4; q++) acc[i][j][q] = 0.0f;

    // stage loader: 768 x 16B cp.async (3 per thread); A = 256 chunks, B = 512
    auto load_stage = [&](int s, int k0) {
        uint32_t base = sbase + s * STAGE2;
        #pragma unroll
        for (int q3 = 0; q3 < 3; q3++) {
            int idx = q3 * 256 + tid;
            if (idx < 256) {
                int row  = idx >> 2;
                int quar = idx & 3;
                uint32_t dst = base + row * ROWB32 + quar * 16;
                int grow = row0 + row;
                int srow = grow < M ? grow : (M - 1);
                const __half* src = A + (size_t)srow * 512 + k0 + quar * 8;
                cp16(dst, src, grow < M ? 16u : 0u);
            } else {
                int slot = idx - 256;
                int row  = slot >> 2;
                int quar = slot & 3;
                uint32_t dst = base + MATA2 + row * ROWB32 + quar * 16;
                const __half* src = B + (size_t)row * 512 + k0 + quar * 8;
                cp16(dst, src, 16u);
            }
        }
    };

    load_stage(0, 0);
    cp_commit();

    #pragma unroll 1
    for (int c = 0; c < 16; c++) {
        if (c < 15) {
            load_stage((c + 1) & 1, (c + 1) * 32);
            cp_commit();
            cp_wait<1>();
        } else {
            cp_wait<0>();
        }
        __syncthreads();

        const uint32_t st = sbase + (c & 1) * STAGE2;
        const uint32_t uA = st;
        const uint32_t uB = st + MATA2;

        #pragma unroll
        for (int kk = 0; kk < 32; kk += 16) {
            const uint32_t kb = (uint32_t)(kk * 2) + lmc;
            uint32_t b2[2][4];
            #pragma unroll
            for (int pp = 0; pp < 2; pp++) {
                uint32_t nb = (uint32_t)((wn * 32 + pp * 16) * ROWB32) + kb;
                ldsm4(b2[pp], uB + nb);
            }
            #pragma unroll
            for (int i = 0; i < 2; i++) {
                uint32_t rb = (uint32_t)((wm * 32 + i * 16) * ROWB32) + kb;
                uint32_t ah[4];
                ldsm4(ah, uA + rb);
                #pragma unroll
                for (int j = 0; j < 4; j++) {
                    const int pp = j >> 1, s = j & 1;
                    uint32_t bb[2] = { b2[pp][s], b2[pp][s + 2] };
                    mma16816h(acc[i][j], ah, bb);
                }
            }
        }
        __syncthreads();
    }

    #pragma unroll
    for (int j = 0; j < 4; j++) {
        int cidx = wn * 32 + j * 8 + 2 * t;
        float bx = bias[cidx], by = bias[cidx + 1];
        #pragma unroll
        for (int i = 0; i < 2; i++) {
            int r = row0 + wm * 32 + i * 16 + g;
            float v0 = 1.0f / (1.0f + expf(-(acc[i][j][0] + bx)));
            float v1 = 1.0f / (1.0f + expf(-(acc[i][j][1] + by)));
            float v2 = 1.0f / (1.0f + expf(-(acc[i][j][2] + bx)));
            float v3 = 1.0f / (1.0f + expf(-(acc[i][j][3] + by)));
            if (r < M)
                *(float2*)(C + (size_t)r * DOUTc + cidx) = make_float2(v0, v1);
            if (r + 8 < M)
                *(float2*)(C + (size_t)(r + 8) * DOUTc + cidx) = make_float2(v2, v3);
        }
    }
}

// ---------------- launch ----------------------------------------------------------

extern "C" void kernel_launch(void* const* d_in, const int* in_sizes, int n_in,
                              void* d_out, int out_size) {
    const float* x    = (const float*)d_in[0];
    const float* W1l  = (const float*)d_in[1];
    const float* b1   = (const float*)d_in[2];
    const float* W1r  = (const float*)d_in[3];
    const float* W2l  = (const float*)d_in[4];
    const float* b2   = (const float*)d_in[5];
    const float* W2r  = (const float*)d_in[6];
    const int*   src1 = (const int*)d_in[7];
    const int*   dst1 = (const int*)d_in[8];
    const int*   src2 = (const int*)d_in[9];
    const int*   dst2 = (const int*)d_in[10];
    float* out = (float*)d_out;

    void *p;
    __half *xh, *h;
    int *cnt, *offs1, *offs2, *cur1, *cur2, *eid1, *eid2;
    __half *A1, *A2, *W1_, *W2_;
    cudaGetSymbolAddress(&p, g_xh);    xh    = (__half*)p;
    cudaGetSymbolAddress(&p, g_h);     h     = (__half*)p;
    cudaGetSymbolAddress(&p, g_cnt);   cnt   = (int*)p;
    cudaGetSymbolAddress(&p, g_offs1); offs1 = (int*)p;
    cudaGetSymbolAddress(&p, g_offs2); offs2 = (int*)p;
    cudaGetSymbolAddress(&p, g_cur1);  cur1  = (int*)p;
    cudaGetSymbolAddress(&p, g_cur2);  cur2  = (int*)p;
    cudaGetSymbolAddress(&p, g_eid1);  eid1  = (int*)p;
    cudaGetSymbolAddress(&p, g_eid2);  eid2  = (int*)p;
    cudaGetSymbolAddress(&p, g_A1);    A1    = (__half*)p;
    cudaGetSymbolAddress(&p, g_A2);    A2    = (__half*)p;
    cudaGetSymbolAddress(&p, g_W1);    W1_   = (__half*)p;
    cudaGetSymbolAddress(&p, g_W2);    W2_   = (__half*)p;

    cudaFuncSetAttribute(gemm_mma64, cudaFuncAttributeMaxDynamicSharedMemorySize, SMEM64);
    cudaFuncSetAttribute(gemm2_kernel, cudaFuncAttributeMaxDynamicSharedMemorySize, SMEM2);

    // (0) memset counts + done-counter
    cudaMemsetAsync(cnt, 0, (size_t)(N1c + N2c + 2) * sizeof(int), 0);

    // (1) count + scan + convert-x + convert-W (convert overlaps scan)
    count_scan_conv_kernel<<<CS_BLOCKS, 1024>>>(dst1, dst2, cnt, offs1, cur1, offs2, cur2,
                                                x, xh, W1l, W1r, W1_, W2l, W2r, W2_);
    // (2) fill both edge-id arrays
    fill_both_kernel<<<(E1c + E2c + 255) / 256, 256>>>(src1, dst1, src2, dst2,
                                                       cur1, cur2, eid1, eid2);
    // (3) gather1 (fp16 rows)
    gather1_kernel<<<GATHER1_BLOCKS, 256>>>(xh, offs1, eid1, A1);
    // (4) gemm1 -> fp16 h (persistent BK=64: 626 tiles on 592 CTAs)
    {
        int nTiles = ((N1c + 127) / 128) * 2;   // 626
        gemm_mma64<<<592, 256, SMEM64>>>(A1, W1_, b1, h, N1c, nTiles);
    }
    // (5) gather2
    gather2_kernel<<<(N2c * 32 + 255) / 256, 256>>>(h, offs2, eid2, A2);
    // (6) gemm2 -> fp32 out (BM=64: 157 CTAs)
    {
        dim3 grid(1, (N2c + 63) / 64);          // 157
        gemm2_kernel<<<grid, 256, SMEM2>>>(A2, W2_, b2, out, N2c);
    }
}

// round 15
// speedup vs baseline: 1.1616x; 1.0246x over previous
#include <cuda_runtime.h>
#include <cuda_fp16.h>
#include <cstdint>
#include <math.h>

// Problem constants
#define N0c 100000
#define N1c 40000
#define N2c 10000
#define E1c 640000
#define E2c 160000
#define Dc  256
#define DOUTc 128

#define GATHER1_BLOCKS (N1c / 8)   // 5000 (8 warps/block, 1 warp per dst row)
#define CS_BLOCKS      148

// ---------------- scratch (device globals) -----------------------------------
__device__ __half g_xh[(size_t)N0c * Dc];   // fp16 copy of x
__device__ __half g_h[(size_t)N1c * Dc];    // fp16 hidden layer
__device__ int   g_cnt[N1c + N2c + 2];      // counts + done-counter (zeroed by fill)
__device__ int   g_offs1[N1c + 1];
__device__ int   g_offs2[N2c + 1];
__device__ int   g_cur1[N1c];
__device__ int   g_cur2[N2c];
__device__ int   g_eid1[E1c];
__device__ int   g_eid2[E2c];

__device__ __half g_A1[(size_t)N1c * 512];
__device__ __half g_A2[(size_t)N2c * 512];
__device__ __half g_W1[(size_t)Dc * 512];
__device__ __half g_W2[(size_t)DOUTc * 512];

// ---------------- PTX helpers ---------------------------------------------------

__device__ __forceinline__ uint32_t smem_u32(const void* p) {
    uint32_t a;
    asm("{ .reg .u64 t; cvta.to.shared.u64 t, %1; cvt.u32.u64 %0, t; }" : "=r"(a) : "l"(p));
    return a;
}

__device__ __forceinline__ void cp16(uint32_t dst, const void* src, uint32_t sz) {
    asm volatile("cp.async.ca.shared.global [%0], [%1], 16, %2;"
                 :: "r"(dst), "l"(src), "r"(sz) : "memory");
}
__device__ __forceinline__ void cp_commit() {
    asm volatile("cp.async.commit_group;" ::: "memory");
}
template <int N>
__device__ __forceinline__ void cp_wait() {
    asm volatile("cp.async.wait_group %0;" :: "n"(N) : "memory");
}

__device__ __forceinline__ void mma16816h(float* c, const uint32_t* a, const uint32_t* b) {
    asm volatile(
        "mma.sync.aligned.m16n8k16.row.col.f32.f16.f16.f32 "
        "{%0,%1,%2,%3}, {%4,%5,%6,%7}, {%8,%9}, {%0,%1,%2,%3};"
        : "+f"(c[0]), "+f"(c[1]), "+f"(c[2]), "+f"(c[3])
        : "r"(a[0]), "r"(a[1]), "r"(a[2]), "r"(a[3]), "r"(b[0]), "r"(b[1]));
}

__device__ __forceinline__ void ldsm4(uint32_t* r, uint32_t addr) {
    asm volatile("ldmatrix.sync.aligned.m8n8.x4.shared.b16 {%0,%1,%2,%3}, [%4];"
                 : "=r"(r[0]), "=r"(r[1]), "=r"(r[2]), "=r"(r[3]) : "r"(addr));
}

__device__ __forceinline__ uint32_t pack_h2(float a, float b) {
    __half2 h = __floats2half2_rn(a, b);
    return *(uint32_t*)&h;
}

// ---------------- count + scan + convert (persistent, sw barrier) -----------------

__global__ void count_scan_conv_kernel(const int* __restrict__ dst1,
                                       const int* __restrict__ dst2,
                                       int* __restrict__ cnt,
                                       int* __restrict__ offs1, int* __restrict__ cur1,
                                       int* __restrict__ offs2, int* __restrict__ cur2,
                                       const float* __restrict__ x, __half* __restrict__ xh,
                                       const float* __restrict__ W1l, const float* __restrict__ W1r,
                                       __half* __restrict__ W1_,
                                       const float* __restrict__ W2l, const float* __restrict__ W2r,
                                       __half* __restrict__ W2_) {
    int* done = cnt + N1c + N2c;
    const int total = E1c + E2c;
    for (int i = blockIdx.x * blockDim.x + threadIdx.x; i < total;
         i += gridDim.x * blockDim.x) {
        if (i < E1c) atomicAdd(&cnt[dst1[i]], 1);
        else         atomicAdd(&cnt[N1c + dst2[i - E1c]], 1);
    }
    __syncthreads();
    __threadfence();
    if (threadIdx.x == 0) atomicAdd(done, 1);

    if (blockIdx.x >= 2) {
        // ---- convert phase (overlaps the scans running on blocks 0,1) ----
        const int nt  = (gridDim.x - 2) * blockDim.x;
        const int tg  = (blockIdx.x - 2) * blockDim.x + threadIdx.x;
        const float4* xf = (const float4*)x;
        const int xiters = N0c * Dc / 8;
        for (int i = tg; i < xiters; i += nt) {
            float4 v0 = xf[2 * i];
            float4 v1 = xf[2 * i + 1];
            uint4 u;
            u.x = pack_h2(v0.x, v0.y);
            u.y = pack_h2(v0.z, v0.w);
            u.z = pack_h2(v1.x, v1.y);
            u.w = pack_h2(v1.z, v1.w);
            ((uint4*)xh)[i] = u;
        }
        for (int i = tg; i < Dc * 512; i += nt) {
            int n = i >> 9, k = i & 511;
            float v = (k < 256) ? W1l[(size_t)k * Dc + n] : W1r[(size_t)(k - 256) * Dc + n];
            W1_[(size_t)n * 512 + k] = __float2half_rn(v);
        }
        for (int i = tg; i < DOUTc * 512; i += nt) {
            int n = i >> 9, k = i & 511;
            float v = (k < 256) ? W2l[(size_t)k * DOUTc + n] : W2r[(size_t)(k - 256) * DOUTc + n];
            W2_[(size_t)n * 512 + k] = __float2half_rn(v);
        }
        return;
    }

    // blocks 0,1: wait for all counts, then scan one layer each
    if (threadIdx.x == 0) {
        while (*(volatile int*)done < (int)gridDim.x) { }
    }
    __syncthreads();
    __threadfence();

    const int  n  = (blockIdx.x == 0) ? N1c : N2c;
    const int* c  = (blockIdx.x == 0) ? cnt : (cnt + N1c);
    int* offs = (blockIdx.x == 0) ? offs1 : offs2;
    int* cur  = (blockIdx.x == 0) ? cur1 : cur2;

    __shared__ int warpsums[32];
    __shared__ int s_carry;
    const int lane = threadIdx.x & 31;
    const int wid  = threadIdx.x >> 5;
    const int nw   = blockDim.x >> 5;
    if (threadIdx.x == 0) s_carry = 0;
    __syncthreads();
    for (int base = 0; base < n; base += blockDim.x) {
        int i = base + threadIdx.x;
        int v = (i < n) ? c[i] : 0;
        int carry = s_carry;
        int xv = v;
        #pragma unroll
        for (int o = 1; o < 32; o <<= 1) {
            int y = __shfl_up_sync(0xFFFFFFFFu, xv, o);
            if (lane >= o) xv += y;
        }
        if (lane == 31) warpsums[wid] = xv;
        __syncthreads();
        if (wid == 0) {
            int w = (lane < nw) ? warpsums[lane] : 0;
            #pragma unroll
            for (int o = 1; o < 32; o <<= 1) {
                int y = __shfl_up_sync(0xFFFFFFFFu, w, o);
                if (lane >= o) w += y;
            }
            warpsums[lane] = w;
        }
        __syncthreads();
        int incl = xv + (wid > 0 ? warpsums[wid - 1] : 0) + carry;
        if (i < n) { offs[i] = incl - v; cur[i] = incl - v; }
        __syncthreads();
        if (threadIdx.x == blockDim.x - 1) s_carry = incl;
        __syncthreads();
    }
    if (threadIdx.x == 0) offs[n] = s_carry;
}

// fill + self-clean: zeroes cnt[] (incl. done counter) for the NEXT graph replay.
// cnt is dead after the scans; device globals are zero-init for the very first call.
__global__ void fill_both_kernel(const int* __restrict__ src1, const int* __restrict__ dst1,
                                 const int* __restrict__ src2, const int* __restrict__ dst2,
                                 int* __restrict__ cur1, int* __restrict__ cur2,
                                 int* __restrict__ eid1, int* __restrict__ eid2,
                                 int* __restrict__ cnt) {
    int i = blockIdx.x * blockDim.x + threadIdx.x;
    if (i < N1c + N2c + 2) cnt[i] = 0;   // reset for next replay (stream-ordered)
    if (i < E1c) {
        int pos = atomicAdd(&cur1[dst1[i]], 1);
        eid1[pos] = src1[i];
    } else if (i < E1c + E2c) {
        int j = i - E1c;
        int pos = atomicAdd(&cur2[dst2[j]], 1);
        eid2[pos] = src2[j];
    }
}

// ---------------- fp16 gather-mean (4-edge unrolled, MLP=8) -------------------------

__device__ __forceinline__ void acc8(float* s, uint4 v) {
    __half2* p = (__half2*)&v;
    #pragma unroll
    for (int q = 0; q < 4; q++) {
        float2 f = __half22float2(p[q]);
        s[2 * q]     += f.x;
        s[2 * q + 1] += f.y;
    }
}

__device__ __forceinline__ void gather_row_h(const __half* __restrict__ X,
                                             const int* __restrict__ offs,
                                             const int* __restrict__ eid,
                                             __half* __restrict__ A,
                                             int w, int lane) {
    int beg = offs[w], end = offs[w + 1];
    float s[8];
    #pragma unroll
    for (int q = 0; q < 8; q++) s[q] = 0.0f;

    int e = beg;
    for (; e + 3 < end; e += 4) {
        int i0 = __ldg(&eid[e]);
        int i1 = __ldg(&eid[e + 1]);
        int i2 = __ldg(&eid[e + 2]);
        int i3 = __ldg(&eid[e + 3]);
        uint4 v0 = __ldg((const uint4*)(X + (size_t)i0 * Dc) + lane);
        uint4 v1 = __ldg((const uint4*)(X + (size_t)i1 * Dc) + lane);
        uint4 v2 = __ldg((const uint4*)(X + (size_t)i2 * Dc) + lane);
        uint4 v3 = __ldg((const uint4*)(X + (size_t)i3 * Dc) + lane);
        acc8(s, v0);
        acc8(s, v1);
        acc8(s, v2);
        acc8(s, v3);
    }
    if (e + 1 < end) {
        int i0 = __ldg(&eid[e]);
        int i1 = __ldg(&eid[e + 1]);
        uint4 v0 = __ldg((const uint4*)(X + (size_t)i0 * Dc) + lane);
        uint4 v1 = __ldg((const uint4*)(X + (size_t)i1 * Dc) + lane);
        acc8(s, v0);
        acc8(s, v1);
        e += 2;
    }
    if (e < end) {
        uint4 v0 = __ldg((const uint4*)(X + (size_t)__ldg(&eid[e]) * Dc) + lane);
        acc8(s, v0);
    }
    float invd = 1.0f / (float)max(end - beg, 1);

    uint4 m;
    m.x = pack_h2(s[0] * invd, s[1] * invd);
    m.y = pack_h2(s[2] * invd, s[3] * invd);
    m.z = pack_h2(s[4] * invd, s[5] * invd);
    m.w = pack_h2(s[6] * invd, s[7] * invd);

    uint4 self = __ldg((const uint4*)(X + (size_t)w * Dc) + lane);

    __stcs((uint4*)(A + (size_t)w * 512) + lane, m);
    __stcs((uint4*)(A + (size_t)w * 512 + 256) + lane, self);
}

__global__ void gather1_kernel(const __half* __restrict__ xh,
                               const int* __restrict__ offs1, const int* __restrict__ eid1,
                               __half* __restrict__ A1) {
    int w    = blockIdx.x * 8 + (threadIdx.x >> 5);
    int lane = threadIdx.x & 31;
    if (w < N1c) gather_row_h(xh, offs1, eid1, A1, w, lane);
}

__global__ void gather2_kernel(const __half* __restrict__ h,
                               const int* __restrict__ offs2, const int* __restrict__ eid2,
                               __half* __restrict__ A2) {
    int w    = (blockIdx.x * blockDim.x + threadIdx.x) >> 5;
    int lane = threadIdx.x & 31;
    if (w < N2c) gather_row_h(h, offs2, eid2, A2, w, lane);
}

// ---------------- GEMM 1: persistent mma.sync fp16, BK=64 (R12-verified) ------------

#define ROWB64 144
#define MAT64  (128 * ROWB64)
#define STAGE64 (2 * MAT64)
#define SMEM64  (2 * STAGE64)

__global__ void __launch_bounds__(256, 2)
gemm_mma64(const __half* __restrict__ A, const __half* __restrict__ B,
           const float* __restrict__ bias, __half* __restrict__ C, int M, int nTiles)
{
    extern __shared__ char smem[];
    const uint32_t sbase = smem_u32(smem);
    const int tid  = threadIdx.x;
    const int wid  = tid >> 5;
    const int lane = tid & 31;
    const int wm   = wid >> 2;
    const int wn   = wid & 3;
    const int g    = lane >> 2;
    const int t    = lane & 3;

    const int rowoff = (lane & 7) + ((lane >> 3) & 1) * 8;
    const int koff   = (lane >> 4) * 8;
    const uint32_t lmc = (uint32_t)(rowoff * ROWB64 + koff * 2);

    if ((int)blockIdx.x >= nTiles) return;

    auto load_stage = [&](int s, int k0, int row0, int col0) {
        uint32_t base = sbase + s * STAGE64;
        #pragma unroll
        for (int q8 = 0; q8 < 8; q8++) {
            int idx  = q8 * 256 + tid;
            int mat  = idx >> 10;
            int slot = idx & 1023;
            int row  = slot >> 3;
            int quar = slot & 7;
            uint32_t dst = base + mat * MAT64 + row * ROWB64 + quar * 16;
            if (mat == 0) {
                int grow = row0 + row;
                int srow = grow < M ? grow : (M - 1);
                const __half* src = A + (size_t)srow * 512 + k0 + quar * 8;
                cp16(dst, src, grow < M ? 16u : 0u);
            } else {
                const __half* src = B + (size_t)(col0 + row) * 512 + k0 + quar * 8;
                cp16(dst, src, 16u);
            }
        }
    };

    auto tile_row0 = [&](int tl) { return (tl >> 1) * 128; };
    auto tile_col0 = [&](int tl) { return (tl & 1) * 128; };

    int tile = blockIdx.x;
    load_stage(0, 0, tile_row0(tile), tile_col0(tile));
    cp_commit();

    #pragma unroll 1
    for (; tile < nTiles; tile += gridDim.x) {
        const int row0 = tile_row0(tile);
        const int col0 = tile_col0(tile);
        const int ntile = tile + gridDim.x;

        float acc[4][4][4];
        #pragma unroll
        for (int i = 0; i < 4; i++)
            #pragma unroll
            for (int j = 0; j < 4; j++)
                #pragma unroll
                for (int q = 0; q < 4; q++) acc[i][j][q] = 0.0f;

        #pragma unroll 1
        for (int c = 0; c < 8; c++) {
            if (c < 7) {
                load_stage((c + 1) & 1, (c + 1) * 64, row0, col0);
            } else if (ntile < nTiles) {
                load_stage(0, 0, tile_row0(ntile), tile_col0(ntile));
            }
            cp_commit();
            cp_wait<1>();
            __syncthreads();

            const uint32_t st = sbase + (c & 1) * STAGE64;
            const uint32_t uA = st;
            const uint32_t uB = st + MAT64;

            #pragma unroll
            for (int kk = 0; kk < 64; kk += 16) {
                const uint32_t kb = (uint32_t)(kk * 2) + lmc;
                uint32_t b2[2][4];
                #pragma unroll
                for (int pp = 0; pp < 2; pp++) {
                    uint32_t nb = (uint32_t)((wn * 32 + pp * 16) * ROWB64) + kb;
                    ldsm4(b2[pp], uB + nb);
                }
                #pragma unroll
                for (int i = 0; i < 4; i++) {
                    uint32_t rb = (uint32_t)((wm * 64 + i * 16) * ROWB64) + kb;
                    uint32_t ah[4];
                    ldsm4(ah, uA + rb);
                    #pragma unroll
                    for (int j = 0; j < 4; j++) {
                        const int pp = j >> 1, s = j & 1;
                        uint32_t bb[2] = { b2[pp][s], b2[pp][s + 2] };
                        mma16816h(acc[i][j], ah, bb);
                    }
                }
            }
            __syncthreads();
        }

        #pragma unroll
        for (int j = 0; j < 4; j++) {
            int cidx = col0 + wn * 32 + j * 8 + 2 * t;
            float bx = bias[cidx], by = bias[cidx + 1];
            #pragma unroll
            for (int i = 0; i < 4; i++) {
                int r = row0 + wm * 64 + i * 16 + g;
                float v0 = fmaxf(acc[i][j][0] + bx, 0.f);
                float v1 = fmaxf(acc[i][j][1] + by, 0.f);
                float v2 = fmaxf(acc[i][j][2] + bx, 0.f);
                float v3 = fmaxf(acc[i][j][3] + by, 0.f);
                if (r < M)
                    *(uint32_t*)(C + (size_t)r * 256 + cidx) = pack_h2(v0, v1);
                if (r + 8 < M)
                    *(uint32_t*)(C + (size_t)(r + 8) * 256 + cidx) = pack_h2(v2, v3);
            }
        }
    }
}

// ---------------- GEMM 2: mma.sync fp16, BM=64, BK=32 (157 CTAs, R14-verified) ------

#define ROWB32 80
#define MATA2  (64 * ROWB32)
#define MATB2  (128 * ROWB32)
#define STAGE2 (MATA2 + MATB2)
#define SMEM2  (2 * STAGE2)

__global__ void __launch_bounds__(256, 2)
gemm2_kernel(const __half* __restrict__ A, const __half* __restrict__ B,
             const float* __restrict__ bias, float* __restrict__ C, int M)
{
    extern __shared__ char smem[];
    const uint32_t sbase = smem_u32(smem);
    const int tid  = threadIdx.x;
    const int wid  = tid >> 5;
    const int lane = tid & 31;
    const int wm   = wid >> 2;
    const int wn   = wid & 3;
    const int g    = lane >> 2;
    const int t    = lane & 3;

    const int row0 = blockIdx.y * 64;

    const int rowoff = (lane & 7) + ((lane >> 3) & 1) * 8;
    const int koff   = (lane >> 4) * 8;
    const uint32_t lmc = (uint32_t)(rowoff * ROWB32 + koff * 2);

    float acc[2][4][4];
    #pragma unroll
    for (int i = 0; i < 2; i++)
        #pragma unroll
        for (int j = 0; j < 4; j++)
            #pragma unroll
            for (int q = 0; q < 4; q++) acc[i][j][q] = 0.0f;

    auto load_stage = [&](int s, int k0) {
        uint32_t base = sbase + s * STAGE2;
        #pragma unroll
        for (int q3 = 0; q3 < 3; q3++) {
            int idx = q3 * 256 + tid;
            if (idx < 256) {
                int row  = idx >> 2;
                int quar = idx & 3;
                uint32_t dst = base + row * ROWB32 + quar * 16;
                int grow = row0 + row;
                int srow = grow < M ? grow : (M - 1);
                const __half* src = A + (size_t)srow * 512 + k0 + quar * 8;
                cp16(dst, src, grow < M ? 16u : 0u);
            } else {
                int slot = idx - 256;
                int row  = slot >> 2;
                int quar = slot & 3;
                uint32_t dst = base + MATA2 + row * ROWB32 + quar * 16;
                const __half* src = B + (size_t)row * 512 + k0 + quar * 8;
                cp16(dst, src, 16u);
            }
        }
    };

    load_stage(0, 0);
    cp_commit();

    #pragma unroll 1
    for (int c = 0; c < 16; c++) {
        if (c < 15) {
            load_stage((c + 1) & 1, (c + 1) * 32);
            cp_commit();
            cp_wait<1>();
        } else {
            cp_wait<0>();
        }
        __syncthreads();

        const uint32_t st = sbase + (c & 1) * STAGE2;
        const uint32_t uA = st;
        const uint32_t uB = st + MATA2;

        #pragma unroll
        for (int kk = 0; kk < 32; kk += 16) {
            const uint32_t kb = (uint32_t)(kk * 2) + lmc;
            uint32_t b2[2][4];
            #pragma unroll
            for (int pp = 0; pp < 2; pp++) {
                uint32_t nb = (uint32_t)((wn * 32 + pp * 16) * ROWB32) + kb;
                ldsm4(b2[pp], uB + nb);
            }
            #pragma unroll
            for (int i = 0; i < 2; i++) {
                uint32_t rb = (uint32_t)((wm * 32 + i * 16) * ROWB32) + kb;
                uint32_t ah[4];
                ldsm4(ah, uA + rb);
                #pragma unroll
                for (int j = 0; j < 4; j++) {
                    const int pp = j >> 1, s = j & 1;
                    uint32_t bb[2] = { b2[pp][s], b2[pp][s + 2] };
                    mma16816h(acc[i][j], ah, bb);
                }
            }
        }
        __syncthreads();
    }

    #pragma unroll
    for (int j = 0; j < 4; j++) {
        int cidx = wn * 32 + j * 8 + 2 * t;
        float bx = bias[cidx], by = bias[cidx + 1];
        #pragma unroll
        for (int i = 0; i < 2; i++) {
            int r = row0 + wm * 32 + i * 16 + g;
            float v0 = 1.0f / (1.0f + expf(-(acc[i][j][0] + bx)));
            float v1 = 1.0f / (1.0f + expf(-(acc[i][j][1] + by)));
            float v2 = 1.0f / (1.0f + expf(-(acc[i][j][2] + bx)));
            float v3 = 1.0f / (1.0f + expf(-(acc[i][j][3] + by)));
            if (r < M)
                *(float2*)(C + (size_t)r * DOUTc + cidx) = make_float2(v0, v1);
            if (r + 8 < M)
                *(float2*)(C + (size_t)(r + 8) * DOUTc + cidx) = make_float2(v2, v3);
        }
    }
}

// ---------------- launch ----------------------------------------------------------

extern "C" void kernel_launch(void* const* d_in, const int* in_sizes, int n_in,
                              void* d_out, int out_size) {
    const float* x    = (const float*)d_in[0];
    const float* W1l  = (const float*)d_in[1];
    const float* b1   = (const float*)d_in[2];
    const float* W1r  = (const float*)d_in[3];
    const float* W2l  = (const float*)d_in[4];
    const float* b2   = (const float*)d_in[5];
    const float* W2r  = (const float*)d_in[6];
    const int*   src1 = (const int*)d_in[7];
    const int*   dst1 = (const int*)d_in[8];
    const int*   src2 = (const int*)d_in[9];
    const int*   dst2 = (const int*)d_in[10];
    float* out = (float*)d_out;

    void *p;
    __half *xh, *h;
    int *cnt, *offs1, *offs2, *cur1, *cur2, *eid1, *eid2;
    __half *A1, *A2, *W1_, *W2_;
    cudaGetSymbolAddress(&p, g_xh);    xh    = (__half*)p;
    cudaGetSymbolAddress(&p, g_h);     h     = (__half*)p;
    cudaGetSymbolAddress(&p, g_cnt);   cnt   = (int*)p;
    cudaGetSymbolAddress(&p, g_offs1); offs1 = (int*)p;
    cudaGetSymbolAddress(&p, g_offs2); offs2 = (int*)p;
    cudaGetSymbolAddress(&p, g_cur1);  cur1  = (int*)p;
    cudaGetSymbolAddress(&p, g_cur2);  cur2  = (int*)p;
    cudaGetSymbolAddress(&p, g_eid1);  eid1  = (int*)p;
    cudaGetSymbolAddress(&p, g_eid2);  eid2  = (int*)p;
    cudaGetSymbolAddress(&p, g_A1);    A1    = (__half*)p;
    cudaGetSymbolAddress(&p, g_A2);    A2    = (__half*)p;
    cudaGetSymbolAddress(&p, g_W1);    W1_   = (__half*)p;
    cudaGetSymbolAddress(&p, g_W2);    W2_   = (__half*)p;

    cudaFuncSetAttribute(gemm_mma64, cudaFuncAttributeMaxDynamicSharedMemorySize, SMEM64);
    cudaFuncSetAttribute(gemm2_kernel, cudaFuncAttributeMaxDynamicSharedMemorySize, SMEM2);

    // (1) count + scan + convert-x + convert-W (cnt pre-zeroed: globals zero-init,
    //     then fill_both re-zeroes it every replay -> no memset node needed)
    count_scan_conv_kernel<<<CS_BLOCKS, 1024>>>(dst1, dst2, cnt, offs1, cur1, offs2, cur2,
                                                x, xh, W1l, W1r, W1_, W2l, W2r, W2_);
    // (2) fill both edge-id arrays + self-clean cnt for next replay
    fill_both_kernel<<<(E1c + E2c + 255) / 256, 256>>>(src1, dst1, src2, dst2,
                                                       cur1, cur2, eid1, eid2, cnt);
    // (3) gather1 (fp16 rows, MLP=8)
    gather1_kernel<<<GATHER1_BLOCKS, 256>>>(xh, offs1, eid1, A1);
    // (4) gemm1 -> fp16 h (persistent BK=64: 626 tiles on 592 CTAs)
    {
        int nTiles = ((N1c + 127) / 128) * 2;   // 626
        gemm_mma64<<<592, 256, SMEM64>>>(A1, W1_, b1, h, N1c, nTiles);
    }
    // (5) gather2 (MLP=8)
    gather2_kernel<<<(N2c * 32 + 255) / 256, 256>>>(h, offs2, eid2, A2);
    // (6) gemm2 -> fp32 out (BM=64: 157 CTAs)
    {
        dim3 grid(1, (N2c + 63) / 64);          // 157
        gemm2_kernel<<<grid, 256, SMEM2>>>(A2, W2_, b2, out, N2c);
    }
}

// round 16
// speedup vs baseline: 1.1758x; 1.0123x over previous
#include <cuda_runtime.h>
#include <cuda_fp16.h>
#include <cstdint>
#include <math.h>

// Problem constants
#define N0c 100000
#define N1c 40000
#define N2c 10000
#define E1c 640000
#define E2c 160000
#define Dc  256
#define DOUTc 128

#define GATHER1_BLOCKS (N1c / 8)   // 5000 (8 warps/block, 1 warp per dst row)
#define CS_BLOCKS      148

// ---------------- scratch (device globals) -----------------------------------
__device__ __half g_xh[(size_t)N0c * Dc];   // fp16 copy of x (also = "self" half of A1)
__device__ __half g_h[(size_t)N1c * Dc];    // fp16 hidden layer (also = "self" half of A2)
__device__ int   g_cnt[N1c + N2c + 2];      // counts + done-counter (zeroed by fill)
__device__ int   g_offs1[N1c + 1];
__device__ int   g_offs2[N2c + 1];
__device__ int   g_cur1[N1c];
__device__ int   g_cur2[N2c];
__device__ int   g_eid1[E1c];
__device__ int   g_eid2[E2c];

__device__ __half g_A1m[(size_t)N1c * 256]; // mean half only
__device__ __half g_A2m[(size_t)N2c * 256];
__device__ __half g_W1[(size_t)Dc * 512];
__device__ __half g_W2[(size_t)DOUTc * 512];

// ---------------- PTX helpers ---------------------------------------------------

__device__ __forceinline__ uint32_t smem_u32(const void* p) {
    uint32_t a;
    asm("{ .reg .u64 t; cvta.to.shared.u64 t, %1; cvt.u32.u64 %0, t; }" : "=r"(a) : "l"(p));
    return a;
}

__device__ __forceinline__ void cp16(uint32_t dst, const void* src, uint32_t sz) {
    asm volatile("cp.async.ca.shared.global [%0], [%1], 16, %2;"
                 :: "r"(dst), "l"(src), "r"(sz) : "memory");
}
__device__ __forceinline__ void cp_commit() {
    asm volatile("cp.async.commit_group;" ::: "memory");
}
template <int N>
__device__ __forceinline__ void cp_wait() {
    asm volatile("cp.async.wait_group %0;" :: "n"(N) : "memory");
}

__device__ __forceinline__ void mma16816h(float* c, const uint32_t* a, const uint32_t* b) {
    asm volatile(
        "mma.sync.aligned.m16n8k16.row.col.f32.f16.f16.f32 "
        "{%0,%1,%2,%3}, {%4,%5,%6,%7}, {%8,%9}, {%0,%1,%2,%3};"
        : "+f"(c[0]), "+f"(c[1]), "+f"(c[2]), "+f"(c[3])
        : "r"(a[0]), "r"(a[1]), "r"(a[2]), "r"(a[3]), "r"(b[0]), "r"(b[1]));
}

__device__ __forceinline__ void ldsm4(uint32_t* r, uint32_t addr) {
    asm volatile("ldmatrix.sync.aligned.m8n8.x4.shared.b16 {%0,%1,%2,%3}, [%4];"
                 : "=r"(r[0]), "=r"(r[1]), "=r"(r[2]), "=r"(r[3]) : "r"(addr));
}

__device__ __forceinline__ uint32_t pack_h2(float a, float b) {
    __half2 h = __floats2half2_rn(a, b);
    return *(uint32_t*)&h;
}

// ---------------- count + scan + convert (persistent, sw barrier) -----------------

__global__ void count_scan_conv_kernel(const int* __restrict__ dst1,
                                       const int* __restrict__ dst2,
                                       int* __restrict__ cnt,
                                       int* __restrict__ offs1, int* __restrict__ cur1,
                                       int* __restrict__ offs2, int* __restrict__ cur2,
                                       const float* __restrict__ x, __half* __restrict__ xh,
                                       const float* __restrict__ W1l, const float* __restrict__ W1r,
                                       __half* __restrict__ W1_,
                                       const float* __restrict__ W2l, const float* __restrict__ W2r,
                                       __half* __restrict__ W2_) {
    int* done = cnt + N1c + N2c;
    const int total = E1c + E2c;
    for (int i = blockIdx.x * blockDim.x + threadIdx.x; i < total;
         i += gridDim.x * blockDim.x) {
        if (i < E1c) atomicAdd(&cnt[dst1[i]], 1);
        else         atomicAdd(&cnt[N1c + dst2[i - E1c]], 1);
    }
    __syncthreads();
    __threadfence();
    if (threadIdx.x == 0) atomicAdd(done, 1);

    if (blockIdx.x >= 2) {
        // ---- convert phase (overlaps the scans running on blocks 0,1) ----
        const int nt  = (gridDim.x - 2) * blockDim.x;
        const int tg  = (blockIdx.x - 2) * blockDim.x + threadIdx.x;
        const float4* xf = (const float4*)x;
        const int xiters = N0c * Dc / 8;
        for (int i = tg; i < xiters; i += nt) {
            float4 v0 = xf[2 * i];
            float4 v1 = xf[2 * i + 1];
            uint4 u;
            u.x = pack_h2(v0.x, v0.y);
            u.y = pack_h2(v0.z, v0.w);
            u.z = pack_h2(v1.x, v1.y);
            u.w = pack_h2(v1.z, v1.w);
            ((uint4*)xh)[i] = u;
        }
        for (int i = tg; i < Dc * 512; i += nt) {
            int n = i >> 9, k = i & 511;
            float v = (k < 256) ? W1l[(size_t)k * Dc + n] : W1r[(size_t)(k - 256) * Dc + n];
            W1_[(size_t)n * 512 + k] = __float2half_rn(v);
        }
        for (int i = tg; i < DOUTc * 512; i += nt) {
            int n = i >> 9, k = i & 511;
            float v = (k < 256) ? W2l[(size_t)k * DOUTc + n] : W2r[(size_t)(k - 256) * DOUTc + n];
            W2_[(size_t)n * 512 + k] = __float2half_rn(v);
        }
        return;
    }

    // blocks 0,1: wait for all counts, then scan one layer each
    if (threadIdx.x == 0) {
        while (*(volatile int*)done < (int)gridDim.x) { }
    }
    __syncthreads();
    __threadfence();

    const int  n  = (blockIdx.x == 0) ? N1c : N2c;
    const int* c  = (blockIdx.x == 0) ? cnt : (cnt + N1c);
    int* offs = (blockIdx.x == 0) ? offs1 : offs2;
    int* cur  = (blockIdx.x == 0) ? cur1 : cur2;

    __shared__ int warpsums[32];
    __shared__ int s_carry;
    const int lane = threadIdx.x & 31;
    const int wid  = threadIdx.x >> 5;
    const int nw   = blockDim.x >> 5;
    if (threadIdx.x == 0) s_carry = 0;
    __syncthreads();
    for (int base = 0; base < n; base += blockDim.x) {
        int i = base + threadIdx.x;
        int v = (i < n) ? c[i] : 0;
        int carry = s_carry;
        int xv = v;
        #pragma unroll
        for (int o = 1; o < 32; o <<= 1) {
            int y = __shfl_up_sync(0xFFFFFFFFu, xv, o);
            if (lane >= o) xv += y;
        }
        if (lane == 31) warpsums[wid] = xv;
        __syncthreads();
        if (wid == 0) {
            int w = (lane < nw) ? warpsums[lane] : 0;
            #pragma unroll
            for (int o = 1; o < 32; o <<= 1) {
                int y = __shfl_up_sync(0xFFFFFFFFu, w, o);
                if (lane >= o) w += y;
            }
            warpsums[lane] = w;
        }
        __syncthreads();
        int incl = xv + (wid > 0 ? warpsums[wid - 1] : 0) + carry;
        if (i < n) { offs[i] = incl - v; cur[i] = incl - v; }
        __syncthreads();
        if (threadIdx.x == blockDim.x - 1) s_carry = incl;
        __syncthreads();
    }
    if (threadIdx.x == 0) offs[n] = s_carry;
}

// fill + self-clean: zeroes cnt[] (incl. done counter) for the NEXT graph replay.
__global__ void fill_both_kernel(const int* __restrict__ src1, const int* __restrict__ dst1,
                                 const int* __restrict__ src2, const int* __restrict__ dst2,
                                 int* __restrict__ cur1, int* __restrict__ cur2,
                                 int* __restrict__ eid1, int* __restrict__ eid2,
                                 int* __restrict__ cnt) {
    int i = blockIdx.x * blockDim.x + threadIdx.x;
    if (i < N1c + N2c + 2) cnt[i] = 0;   // reset for next replay (stream-ordered)
    if (i < E1c) {
        int pos = atomicAdd(&cur1[dst1[i]], 1);
        eid1[pos] = src1[i];
    } else if (i < E1c + E2c) {
        int j = i - E1c;
        int pos = atomicAdd(&cur2[dst2[j]], 1);
        eid2[pos] = src2[j];
    }
}

// ---------------- fp16 gather-mean (mean half only; self read by GEMM directly) ----

__device__ __forceinline__ void acc8(float* s, uint4 v) {
    __half2* p = (__half2*)&v;
    #pragma unroll
    for (int q = 0; q < 4; q++) {
        float2 f = __half22float2(p[q]);
        s[2 * q]     += f.x;
        s[2 * q + 1] += f.y;
    }
}

__device__ __forceinline__ void gather_row_h(const __half* __restrict__ X,
                                             const int* __restrict__ offs,
                                             const int* __restrict__ eid,
                                             __half* __restrict__ Am,
                                             int w, int lane) {
    int beg = offs[w], end = offs[w + 1];
    float s[8];
    #pragma unroll
    for (int q = 0; q < 8; q++) s[q] = 0.0f;

    int e = beg;
    for (; e + 3 < end; e += 4) {
        int i0 = __ldg(&eid[e]);
        int i1 = __ldg(&eid[e + 1]);
        int i2 = __ldg(&eid[e + 2]);
        int i3 = __ldg(&eid[e + 3]);
        uint4 v0 = __ldg((const uint4*)(X + (size_t)i0 * Dc) + lane);
        uint4 v1 = __ldg((const uint4*)(X + (size_t)i1 * Dc) + lane);
        uint4 v2 = __ldg((const uint4*)(X + (size_t)i2 * Dc) + lane);
        uint4 v3 = __ldg((const uint4*)(X + (size_t)i3 * Dc) + lane);
        acc8(s, v0);
        acc8(s, v1);
        acc8(s, v2);
        acc8(s, v3);
    }
    if (e + 1 < end) {
        int i0 = __ldg(&eid[e]);
        int i1 = __ldg(&eid[e + 1]);
        uint4 v0 = __ldg((const uint4*)(X + (size_t)i0 * Dc) + lane);
        uint4 v1 = __ldg((const uint4*)(X + (size_t)i1 * Dc) + lane);
        acc8(s, v0);
        acc8(s, v1);
        e += 2;
    }
    if (e < end) {
        uint4 v0 = __ldg((const uint4*)(X + (size_t)__ldg(&eid[e]) * Dc) + lane);
        acc8(s, v0);
    }
    float invd = 1.0f / (float)max(end - beg, 1);

    uint4 m;
    m.x = pack_h2(s[0] * invd, s[1] * invd);
    m.y = pack_h2(s[2] * invd, s[3] * invd);
    m.z = pack_h2(s[4] * invd, s[5] * invd);
    m.w = pack_h2(s[6] * invd, s[7] * invd);

    __stcs((uint4*)(Am + (size_t)w * 256) + lane, m);
}

__global__ void gather1_kernel(const __half* __restrict__ xh,
                               const int* __restrict__ offs1, const int* __restrict__ eid1,
                               __half* __restrict__ A1m) {
    int w    = blockIdx.x * 8 + (threadIdx.x >> 5);
    int lane = threadIdx.x & 31;
    if (w < N1c) gather_row_h(xh, offs1, eid1, A1m, w, lane);
}

__global__ void gather2_kernel(const __half* __restrict__ h,
                               const int* __restrict__ offs2, const int* __restrict__ eid2,
                               __half* __restrict__ A2m) {
    int w    = (blockIdx.x * blockDim.x + threadIdx.x) >> 5;
    int lane = threadIdx.x & 31;
    if (w < N2c) gather_row_h(h, offs2, eid2, A2m, w, lane);
}

// ---------------- GEMM 1: persistent mma.sync fp16, BK=64 ---------------------------
// A is logically [Am | Xs] (mean | self), both M x 256 fp16 row-major.

#define ROWB64 144
#define MAT64  (128 * ROWB64)
#define STAGE64 (2 * MAT64)
#define SMEM64  (2 * STAGE64)

__global__ void __launch_bounds__(256, 2)
gemm_mma64(const __half* __restrict__ Am, const __half* __restrict__ Xs,
           const __half* __restrict__ B,
           const float* __restrict__ bias, __half* __restrict__ C, int M, int nTiles)
{
    extern __shared__ char smem[];
    const uint32_t sbase = smem_u32(smem);
    const int tid  = threadIdx.x;
    const int wid  = tid >> 5;
    const int lane = tid & 31;
    const int wm   = wid >> 2;
    const int wn   = wid & 3;
    const int g    = lane >> 2;
    const int t    = lane & 3;

    const int rowoff = (lane & 7) + ((lane >> 3) & 1) * 8;
    const int koff   = (lane >> 4) * 8;
    const uint32_t lmc = (uint32_t)(rowoff * ROWB64 + koff * 2);

    if ((int)blockIdx.x >= nTiles) return;

    // chunk k0 in {0,64,128,192} -> Am ; {256,...} -> Xs (64-chunks never straddle 256)
    auto load_stage = [&](int s, int k0, int row0, int col0) {
        uint32_t base = sbase + s * STAGE64;
        const __half* Asrc = (k0 < 256) ? Am : Xs;
        const int     kk0  = k0 & 255;
        #pragma unroll
        for (int q8 = 0; q8 < 8; q8++) {
            int idx  = q8 * 256 + tid;
            int mat  = idx >> 10;
            int slot = idx & 1023;
            int row  = slot >> 3;
            int quar = slot & 7;
            uint32_t dst = base + mat * MAT64 + row * ROWB64 + quar * 16;
            if (mat == 0) {
                int grow = row0 + row;
                int srow = grow < M ? grow : (M - 1);
                const __half* src = Asrc + (size_t)srow * 256 + kk0 + quar * 8;
                cp16(dst, src, grow < M ? 16u : 0u);
            } else {
                const __half* src = B + (size_t)(col0 + row) * 512 + k0 + quar * 8;
                cp16(dst, src, 16u);
            }
        }
    };

    auto tile_row0 = [&](int tl) { return (tl >> 1) * 128; };
    auto tile_col0 = [&](int tl) { return (tl & 1) * 128; };

    int tile = blockIdx.x;
    load_stage(0, 0, tile_row0(tile), tile_col0(tile));
    cp_commit();

    #pragma unroll 1
    for (; tile < nTiles; tile += gridDim.x) {
        const int row0 = tile_row0(tile);
        const int col0 = tile_col0(tile);
        const int ntile = tile + gridDim.x;

        float acc[4][4][4];
        #pragma unroll
        for (int i = 0; i < 4; i++)
            #pragma unroll
            for (int j = 0; j < 4; j++)
                #pragma unroll
                for (int q = 0; q < 4; q++) acc[i][j][q] = 0.0f;

        #pragma unroll 1
        for (int c = 0; c < 8; c++) {
            if (c < 7) {
                load_stage((c + 1) & 1, (c + 1) * 64, row0, col0);
            } else if (ntile < nTiles) {
                load_stage(0, 0, tile_row0(ntile), tile_col0(ntile));
            }
            cp_commit();
            cp_wait<1>();
            __syncthreads();

            const uint32_t st = sbase + (c & 1) * STAGE64;
            const uint32_t uA = st;
            const uint32_t uB = st + MAT64;

            #pragma unroll
            for (int kk = 0; kk < 64; kk += 16) {
                const uint32_t kb = (uint32_t)(kk * 2) + lmc;
                uint32_t b2[2][4];
                #pragma unroll
                for (int pp = 0; pp < 2; pp++) {
                    uint32_t nb = (uint32_t)((wn * 32 + pp * 16) * ROWB64) + kb;
                    ldsm4(b2[pp], uB + nb);
                }
                #pragma unroll
                for (int i = 0; i < 4; i++) {
                    uint32_t rb = (uint32_t)((wm * 64 + i * 16) * ROWB64) + kb;
                    uint32_t ah[4];
                    ldsm4(ah, uA + rb);
                    #pragma unroll
                    for (int j = 0; j < 4; j++) {
                        const int pp = j >> 1, s = j & 1;
                        uint32_t bb[2] = { b2[pp][s], b2[pp][s + 2] };
                        mma16816h(acc[i][j], ah, bb);
                    }
                }
            }
            __syncthreads();
        }

        #pragma unroll
        for (int j = 0; j < 4; j++) {
            int cidx = col0 + wn * 32 + j * 8 + 2 * t;
            float bx = bias[cidx], by = bias[cidx + 1];
            #pragma unroll
            for (int i = 0; i < 4; i++) {
                int r = row0 + wm * 64 + i * 16 + g;
                float v0 = fmaxf(acc[i][j][0] + bx, 0.f);
                float v1 = fmaxf(acc[i][j][1] + by, 0.f);
                float v2 = fmaxf(acc[i][j][2] + bx, 0.f);
                float v3 = fmaxf(acc[i][j][3] + by, 0.f);
                if (r < M)
                    *(uint32_t*)(C + (size_t)r * 256 + cidx) = pack_h2(v0, v1);
                if (r + 8 < M)
                    *(uint32_t*)(C + (size_t)(r + 8) * 256 + cidx) = pack_h2(v2, v3);
            }
        }
    }
}

// ---------------- GEMM 2: mma.sync fp16, BM=64, BK=32 (157 CTAs) --------------------
// A logically [Am | Hs], both M x 256 fp16.

#define ROWB32 80
#define MATA2  (64 * ROWB32)
#define MATB2  (128 * ROWB32)
#define STAGE2 (MATA2 + MATB2)
#define SMEM2  (2 * STAGE2)

__global__ void __launch_bounds__(256, 2)
gemm2_kernel(const __half* __restrict__ Am, const __half* __restrict__ Hs,
             const __half* __restrict__ B,
             const float* __restrict__ bias, float* __restrict__ C, int M)
{
    extern __shared__ char smem[];
    const uint32_t sbase = smem_u32(smem);
    const int tid  = threadIdx.x;
    const int wid  = tid >> 5;
    const int lane = tid & 31;
    const int wm   = wid >> 2;
    const int wn   = wid & 3;
    const int g    = lane >> 2;
    const int t    = lane & 3;

    const int row0 = blockIdx.y * 64;

    const int rowoff = (lane & 7) + ((lane >> 3) & 1) * 8;
    const int koff   = (lane >> 4) * 8;
    const uint32_t lmc = (uint32_t)(rowoff * ROWB32 + koff * 2);

    float acc[2][4][4];
    #pragma unroll
    for (int i = 0; i < 2; i++)
        #pragma unroll
        for (int j = 0; j < 4; j++)
            #pragma unroll
            for (int q = 0; q < 4; q++) acc[i][j][q] = 0.0f;

    // chunk k0 in 32-steps; k0<256 -> Am, else Hs
    auto load_stage = [&](int s, int k0) {
        uint32_t base = sbase + s * STAGE2;
        const __half* Asrc = (k0 < 256) ? Am : Hs;
        const int     kk0  = k0 & 255;
        #pragma unroll
        for (int q3 = 0; q3 < 3; q3++) {
            int idx = q3 * 256 + tid;
            if (idx < 256) {
                int row  = idx >> 2;
                int quar = idx & 3;
                uint32_t dst = base + row * ROWB32 + quar * 16;
                int grow = row0 + row;
                int srow = grow < M ? grow : (M - 1);
                const __half* src = Asrc + (size_t)srow * 256 + kk0 + quar * 8;
                cp16(dst, src, grow < M ? 16u : 0u);
            } else {
                int slot = idx - 256;
                int row  = slot >> 2;
                int quar = slot & 3;
                uint32_t dst = base + MATA2 + row * ROWB32 + quar * 16;
                const __half* src = B + (size_t)row * 512 + k0 + quar * 8;
                cp16(dst, src, 16u);
            }
        }
    };

    load_stage(0, 0);
    cp_commit();

    #pragma unroll 1
    for (int c = 0; c < 16; c++) {
        if (c < 15) {
            load_stage((c + 1) & 1, (c + 1) * 32);
            cp_commit();
            cp_wait<1>();
        } else {
            cp_wait<0>();
        }
        __syncthreads();

        const uint32_t st = sbase + (c & 1) * STAGE2;
        const uint32_t uA = st;
        const uint32_t uB = st + MATA2;

        #pragma unroll
        for (int kk = 0; kk < 32; kk += 16) {
            const uint32_t kb = (uint32_t)(kk * 2) + lmc;
            uint32_t b2[2][4];
            #pragma unroll
            for (int pp = 0; pp < 2; pp++) {
                uint32_t nb = (uint32_t)((wn * 32 + pp * 16) * ROWB32) + kb;
                ldsm4(b2[pp], uB + nb);
            }
            #pragma unroll
            for (int i = 0; i < 2; i++) {
                uint32_t rb = (uint32_t)((wm * 32 + i * 16) * ROWB32) + kb;
                uint32_t ah[4];
                ldsm4(ah, uA + rb);
                #pragma unroll
                for (int j = 0; j < 4; j++) {
                    const int pp = j >> 1, s = j & 1;
                    uint32_t bb[2] = { b2[pp][s], b2[pp][s + 2] };
                    mma16816h(acc[i][j], ah, bb);
                }
            }
        }
        __syncthreads();
    }

    #pragma unroll
    for (int j = 0; j < 4; j++) {
        int cidx = wn * 32 + j * 8 + 2 * t;
        float bx = bias[cidx], by = bias[cidx + 1];
        #pragma unroll
        for (int i = 0; i < 2; i++) {
            int r = row0 + wm * 32 + i * 16 + g;
            float v0 = 1.0f / (1.0f + expf(-(acc[i][j][0] + bx)));
            float v1 = 1.0f / (1.0f + expf(-(acc[i][j][1] + by)));
            float v2 = 1.0f / (1.0f + expf(-(acc[i][j][2] + bx)));
            float v3 = 1.0f / (1.0f + expf(-(acc[i][j][3] + by)));
            if (r < M)
                *(float2*)(C + (size_t)r * DOUTc + cidx) = make_float2(v0, v1);
            if (r + 8 < M)
                *(float2*)(C + (size_t)(r + 8) * DOUTc + cidx) = make_float2(v2, v3);
        }
    }
}

// ---------------- launch ----------------------------------------------------------

extern "C" void kernel_launch(void* const* d_in, const int* in_sizes, int n_in,
                              void* d_out, int out_size) {
    const float* x    = (const float*)d_in[0];
    const float* W1l  = (const float*)d_in[1];
    const float* b1   = (const float*)d_in[2];
    const float* W1r  = (const float*)d_in[3];
    const float* W2l  = (const float*)d_in[4];
    const float* b2   = (const float*)d_in[5];
    const float* W2r  = (const float*)d_in[6];
    const int*   src1 = (const int*)d_in[7];
    const int*   dst1 = (const int*)d_in[8];
    const int*   src2 = (const int*)d_in[9];
    const int*   dst2 = (const int*)d_in[10];
    float* out = (float*)d_out;

    void *p;
    __half *xh, *h;
    int *cnt, *offs1, *offs2, *cur1, *cur2, *eid1, *eid2;
    __half *A1m, *A2m, *W1_, *W2_;
    cudaGetSymbolAddress(&p, g_xh);    xh    = (__half*)p;
    cudaGetSymbolAddress(&p, g_h);     h     = (__half*)p;
    cudaGetSymbolAddress(&p, g_cnt);   cnt   = (int*)p;
    cudaGetSymbolAddress(&p, g_offs1); offs1 = (int*)p;
    cudaGetSymbolAddress(&p, g_offs2); offs2 = (int*)p;
    cudaGetSymbolAddress(&p, g_cur1);  cur1  = (int*)p;
    cudaGetSymbolAddress(&p, g_cur2);  cur2  = (int*)p;
    cudaGetSymbolAddress(&p, g_eid1);  eid1  = (int*)p;
    cudaGetSymbolAddress(&p, g_eid2);  eid2  = (int*)p;
    cudaGetSymbolAddress(&p, g_A1m);   A1m   = (__half*)p;
    cudaGetSymbolAddress(&p, g_A2m);   A2m   = (__half*)p;
    cudaGetSymbolAddress(&p, g_W1);    W1_   = (__half*)p;
    cudaGetSymbolAddress(&p, g_W2);    W2_   = (__half*)p;

    cudaFuncSetAttribute(gemm_mma64, cudaFuncAttributeMaxDynamicSharedMemorySize, SMEM64);
    cudaFuncSetAttribute(gemm2_kernel, cudaFuncAttributeMaxDynamicSharedMemorySize, SMEM2);

    // (1) count + scan + convert (cnt zeroed by fill on previous replay; globals
    //     are zero-initialized for the very first call)
    count_scan_conv_kernel<<<CS_BLOCKS, 1024>>>(dst1, dst2, cnt, offs1, cur1, offs2, cur2,
                                                x, xh, W1l, W1r, W1_, W2l, W2r, W2_);
    // (2) fill both edge-id arrays + self-clean cnt
    fill_both_kernel<<<(E1c + E2c + 255) / 256, 256>>>(src1, dst1, src2, dst2,
                                                       cur1, cur2, eid1, eid2, cnt);
    // (3) gather1: mean half only
    gather1_kernel<<<GATHER1_BLOCKS, 256>>>(xh, offs1, eid1, A1m);
    // (4) gemm1 -> fp16 h (A = [A1m | xh])
    {
        int nTiles = ((N1c + 127) / 128) * 2;   // 626
        gemm_mma64<<<592, 256, SMEM64>>>(A1m, xh, W1_, b1, h, N1c, nTiles);
    }
    // (5) gather2: mean half only
    gather2_kernel<<<(N2c * 32 + 255) / 256, 256>>>(h, offs2, eid2, A2m);
    // (6) gemm2 -> fp32 out (A = [A2m | h])
    {
        dim3 grid(1, (N2c + 63) / 64);          // 157
        gemm2_kernel<<<grid, 256, SMEM2>>>(A2m, h, W2_, b2, out, N2c);
    }
}